// round 7
// baseline (speedup 1.0000x reference)
#include <cuda_runtime.h>
#include <cuda_bf16.h>
#include <cstdint>

// Problem constants
#define Tn 1024
#define Dn 2048
#define Hn 7168
#define En 8
#define Kn 2
#define Pn (Tn * Kn)                   // 2048 (token,k) pairs
#define TILE_M 128
#define MAX_SLOTS (Pn + En * TILE_M)   // 3072
#define MAX_TILES (Pn / TILE_M + En)   // 24

#define G1_KIT (Dn / 32)               // 64 K-chunks of 32
#define G2_KIT (Hn / 32)               // 224 K-chunks of 32

// Dynamic smem: 3 stages x 32KB + 1KB alignment slack (2 CTAs -> 198.7KB/SM)
#define SMEM_REQ (3 * 32768 + 1024)

// Scratch (device globals; no allocation allowed)
__device__ int   g_slot_token[MAX_SLOTS];
__device__ float g_slot_w[MAX_SLOTS];
__device__ int   g_tile_expert[MAX_TILES];
__device__ int   g_tile_base[MAX_TILES];
// bf16 hi/lo planes for the A-side operands (x is tiny; hact produced split)
__device__ __align__(16) unsigned short g_x_hi[(size_t)Tn * Dn];
__device__ __align__(16) unsigned short g_x_lo[(size_t)Tn * Dn];
__device__ __align__(16) unsigned short g_hact_hi[(size_t)MAX_SLOTS * Hn];
__device__ __align__(16) unsigned short g_hact_lo[(size_t)MAX_SLOTS * Hn];

// ---------------------------------------------------------------------------
// Helpers
// ---------------------------------------------------------------------------
__device__ __forceinline__ uint32_t smem_u32(const void* p) {
    uint32_t a;
    asm("{ .reg .u64 t; cvta.to.shared.u64 t, %1; cvt.u32.u64 %0, t; }"
        : "=r"(a) : "l"(p));
    return a;
}

__device__ __forceinline__ uint32_t sw128(uint32_t o) {
    return o ^ (((o >> 7) & 7u) << 4);
}
__device__ __forceinline__ uint32_t sw256(uint32_t o) {
    return o ^ (((o >> 8) & 7u) << 4);
}

__device__ __forceinline__ void cpa16(uint32_t dst, const void* src, uint32_t sz) {
    asm volatile("cp.async.cg.shared.global [%0], [%1], 16, %2;"
                 :: "r"(dst), "l"(src), "r"(sz) : "memory");
}
#define CP_COMMIT() asm volatile("cp.async.commit_group;" ::: "memory")
#define CP_WAIT1()  asm volatile("cp.async.wait_group 1;" ::: "memory")
#define CP_WAIT0()  asm volatile("cp.async.wait_group 0;" ::: "memory")

__device__ __forceinline__ void ldsm4(uint32_t* r, uint32_t a) {
    asm volatile("ldmatrix.sync.aligned.m8n8.x4.shared.b16 {%0,%1,%2,%3}, [%4];"
        : "=r"(r[0]), "=r"(r[1]), "=r"(r[2]), "=r"(r[3]) : "r"(a));
}
__device__ __forceinline__ void ldsm4t(uint32_t* r, uint32_t a) {
    asm volatile("ldmatrix.sync.aligned.m8n8.x4.trans.shared.b16 {%0,%1,%2,%3}, [%4];"
        : "=r"(r[0]), "=r"(r[1]), "=r"(r[2]), "=r"(r[3]) : "r"(a));
}
__device__ __forceinline__ void mma16816(float* c, const uint32_t* a,
                                         uint32_t b0, uint32_t b1) {
    asm volatile(
        "mma.sync.aligned.m16n8k16.row.col.f32.bf16.bf16.f32 "
        "{%0,%1,%2,%3}, {%4,%5,%6,%7}, {%8,%9}, {%0,%1,%2,%3};"
        : "+f"(c[0]), "+f"(c[1]), "+f"(c[2]), "+f"(c[3])
        : "r"(a[0]), "r"(a[1]), "r"(a[2]), "r"(a[3]), "r"(b0), "r"(b1));
}

// bf16 split: hi = truncate(v) (exact in bf16 and fp32), lo = rn(v - hi)
__device__ __forceinline__ uint32_t pack_hi(float a, float b) {
    return (__float_as_uint(a) >> 16) | (__float_as_uint(b) & 0xffff0000u);
}
__device__ __forceinline__ uint32_t pack_lo(float a, float b) {
    float ha = __uint_as_float(__float_as_uint(a) & 0xffff0000u);
    float hb = __uint_as_float(__float_as_uint(b) & 0xffff0000u);
    unsigned short la = __bfloat16_as_ushort(__float2bfloat16(a - ha));
    unsigned short lb = __bfloat16_as_ushort(__float2bfloat16(b - hb));
    return (uint32_t)la | ((uint32_t)lb << 16);
}

// ---------------------------------------------------------------------------
// x split: fp32 -> bf16 hi/lo planes (8 MB, ~8us)
// ---------------------------------------------------------------------------
__global__ void splitx_kernel(const float4* __restrict__ src, int n4) {
    int i = blockIdx.x * blockDim.x + threadIdx.x;
    if (i < n4) {
        float4 v = __ldg(src + i);
        ((uint2*)g_x_hi)[i] = make_uint2(pack_hi(v.x, v.y), pack_hi(v.z, v.w));
        ((uint2*)g_x_lo)[i] = make_uint2(pack_lo(v.x, v.y), pack_lo(v.z, v.w));
    }
}

// ---------------------------------------------------------------------------
// Routing
// ---------------------------------------------------------------------------
__global__ void route_kernel(const int* __restrict__ sel,
                             const float* __restrict__ wts) {
    __shared__ int s_e[Pn];
    __shared__ int s_cnt[En];
    __shared__ int s_base[En];
    int tid = threadIdx.x;

    if (tid < En) s_cnt[tid] = 0;
    __syncthreads();
    for (int i = tid; i < Pn; i += blockDim.x) {
        int e = sel[i];
        s_e[i] = e;
        atomicAdd(&s_cnt[e], 1);
    }
    __syncthreads();
    if (tid == 0) {
        int base = 0, tile = 0;
        for (int e = 0; e < En; e++) {
            s_base[e] = base;
            int padded = ((s_cnt[e] + TILE_M - 1) / TILE_M) * TILE_M;
            for (int m = 0; m < padded; m += TILE_M) {
                g_tile_expert[tile] = e;
                g_tile_base[tile]   = base + m;
                tile++;
            }
            base += padded;
        }
        for (; tile < MAX_TILES; tile++) g_tile_expert[tile] = -1;
    }
    __syncthreads();
    for (int s = tid; s < MAX_SLOTS; s += blockDim.x) g_slot_token[s] = -1;
    __syncthreads();
    for (int i = tid; i < Pn; i += blockDim.x) {
        int e = s_e[i];
        int rank = 0;
        for (int j = 0; j < i; j++) rank += (s_e[j] == e) ? 1 : 0;
        int slot = s_base[e] + rank;
        g_slot_token[slot] = i / Kn;
        g_slot_w[slot]     = wts[i];
    }
}

__global__ void zero_kernel(float* __restrict__ out) {
    int i = blockIdx.x * blockDim.x + threadIdx.x;
    out[i] = 0.0f;
}

// ---------------------------------------------------------------------------
// GEMM1: hact[slot, h0+c] = silu(x.W1^T) * (x.W3^T)
// CTA 128x128 (n 0-63 gate / 64-127 up), BK=32, 4 warps, warp tile 64x64.
// 3-stage pipeline: A (x planes) via cp.async + wait_group 1;
// B (w1/w3 fp32) via reg-staged LDG (distance ~1.2 iters) + convert + STS.
// ---------------------------------------------------------------------------
__global__ __launch_bounds__(128, 2) void gemm1_kernel(
    const float* __restrict__ w1,
    const float* __restrict__ w3) {
    int e = g_tile_expert[blockIdx.x];
    if (e < 0) return;
    int base = g_tile_base[blockIdx.x];
    int h0 = blockIdx.y * 64;

    extern __shared__ char dsm[];
    __shared__ int s_tok[TILE_M];
    uint32_t raw = smem_u32(dsm);
    uint32_t sb = (raw + 1023u) & ~1023u;
    char* sp = dsm + (sb - raw);

    int tid = threadIdx.x;
    s_tok[tid] = g_slot_token[base + tid];
    __syncthreads();

    const int warp = tid >> 5, lane = tid & 31;
    const int wm = warp & 1, wn = warp >> 1;   // 2m x 2n, warp tile 64x64

    // A cp.async: thread t owns row t (hi 64B + lo 64B per chunk)
    const int tok = s_tok[tid];
    const unsigned short* aHs = g_x_hi + (size_t)(tok < 0 ? 0 : tok) * Dn;
    const unsigned short* aLs = g_x_lo + (size_t)(tok < 0 ? 0 : tok) * Dn;
    const uint32_t asz = (tok >= 0) ? 16u : 0u;
    const uint32_t aoff = (uint32_t)tid * 128u;

    // B LDG: thread t owns weight row t (w1 rows 0-63, w3 rows 64-127)
    const float* bP = (tid < 64)
        ? w1 + ((size_t)e * Hn + h0 + tid) * Dn
        : w3 + ((size_t)e * Hn + h0 + tid - 64) * Dn;
    const uint32_t boff = (uint32_t)tid * 128u;

    // ldmatrix lane offsets
    const uint32_t a_m  = (uint32_t)(lane & 15);
    const uint32_t a_kc = (uint32_t)(lane >> 4);
    const uint32_t b_n  = (uint32_t)((lane & 7) | ((lane >> 4) << 3));
    const uint32_t b_kc = (uint32_t)((lane >> 3) & 1);

    float C[4][8][4];
#pragma unroll
    for (int i = 0; i < 4; i++)
#pragma unroll
        for (int j = 0; j < 8; j++)
#pragma unroll
            for (int k = 0; k < 4; k++) C[i][j][k] = 0.f;

    float4 Br[8];

#define LDGB1(c) do {                                                       \
    const float4* q = (const float4*)(bP + (size_t)(c) * 32);               \
    _Pragma("unroll")                                                       \
    for (int i = 0; i < 8; i++) Br[i] = __ldg(q + i);                       \
} while (0)

#define CPA1(c, st) do {                                                    \
    uint32_t Ab = sb + (st) * 32768u;                                       \
    const unsigned short* ah = aHs + (c) * 32;                              \
    const unsigned short* al = aLs + (c) * 32;                              \
    _Pragma("unroll")                                                       \
    for (int g = 0; g < 4; g++) {                                           \
        cpa16(Ab + sw128(aoff + g * 16), ah + g * 8, asz);                  \
        cpa16(Ab + sw128(aoff + 64 + g * 16), al + g * 8, asz);             \
    }                                                                       \
    CP_COMMIT();                                                            \
} while (0)

#define STSB1(st) do {                                                      \
    char* Bb = sp + (st) * 32768 + 16384;                                   \
    _Pragma("unroll")                                                       \
    for (int g = 0; g < 4; g++) {                                           \
        float4 v0 = Br[2 * g], v1 = Br[2 * g + 1];                          \
        uint4 h = make_uint4(pack_hi(v0.x, v0.y), pack_hi(v0.z, v0.w),      \
                             pack_hi(v1.x, v1.y), pack_hi(v1.z, v1.w));     \
        uint4 l = make_uint4(pack_lo(v0.x, v0.y), pack_lo(v0.z, v0.w),      \
                             pack_lo(v1.x, v1.y), pack_lo(v1.z, v1.w));     \
        *(uint4*)(Bb + sw128(boff + g * 16)) = h;                           \
        *(uint4*)(Bb + sw128(boff + 64 + g * 16)) = l;                      \
    }                                                                       \
} while (0)

#define COMP1(st) do {                                                      \
    uint32_t Au = sb + (st) * 32768u;                                       \
    uint32_t Bu = Au + 16384u;                                              \
    _Pragma("unroll")                                                       \
    for (int k16 = 0; k16 < 2; k16++) {                                     \
        uint32_t aH[4][4], aL[4][4];                                        \
        _Pragma("unroll")                                                   \
        for (int mt = 0; mt < 4; mt++) {                                    \
            uint32_t o = (uint32_t)(wm * 64 + mt * 16 + a_m) * 128u + k16 * 32u + a_kc * 16u; \
            ldsm4(aH[mt], Au + sw128(o));                                   \
            ldsm4(aL[mt], Au + sw128(o + 64));                              \
        }                                                                   \
        _Pragma("unroll")                                                   \
        for (int ng = 0; ng < 4; ng++) {                                    \
            uint32_t o = (uint32_t)(wn * 64 + ng * 16 + b_n) * 128u + k16 * 32u + b_kc * 16u; \
            uint32_t bH[4], bL[4];                                          \
            ldsm4(bH, Bu + sw128(o));                                       \
            ldsm4(bL, Bu + sw128(o + 64));                                  \
            _Pragma("unroll")                                               \
            for (int mt = 0; mt < 4; mt++) {                                \
                mma16816(C[mt][2 * ng],     aH[mt], bH[0], bH[1]);          \
                mma16816(C[mt][2 * ng + 1], aH[mt], bH[2], bH[3]);          \
                mma16816(C[mt][2 * ng],     aL[mt], bH[0], bH[1]);          \
                mma16816(C[mt][2 * ng + 1], aL[mt], bH[2], bH[3]);          \
                mma16816(C[mt][2 * ng],     aH[mt], bL[0], bL[1]);          \
                mma16816(C[mt][2 * ng + 1], aH[mt], bL[2], bL[3]);          \
            }                                                               \
        }                                                                   \
    }                                                                       \
} while (0)

    // 3-stage prologue
    LDGB1(0);
    CPA1(0, 0);
    STSB1(0);
    LDGB1(1);
    CPA1(1, 1);
    for (int c = 0; c < G1_KIT; c++) {
        int st = c % 3;
        // oldest in-flight A group (chunk c) must be complete
        if (c + 1 < G1_KIT) CP_WAIT1(); else CP_WAIT0();
        __syncthreads();   // all warps done with COMP(c-1); STSB(c) visible
        if (c + 2 < G1_KIT) CPA1(c + 2, (c + 2) % 3);  // stage freed by COMP(c-1)
        COMP1(st);
        if (c + 1 < G1_KIT) STSB1((c + 1) % 3);
        if (c + 2 < G1_KIT) LDGB1(c + 2);
    }
    __syncthreads();

    // C -> smem fp32 [128][132]
    float* sc = (float*)sp;
#pragma unroll
    for (int mt = 0; mt < 4; mt++)
#pragma unroll
        for (int nt = 0; nt < 8; nt++) {
            int r0 = wm * 64 + mt * 16 + (lane >> 2);
            int cc = wn * 64 + nt * 8 + (lane & 3) * 2;
            sc[r0 * 132 + cc]       = C[mt][nt][0];
            sc[r0 * 132 + cc + 1]   = C[mt][nt][1];
            sc[(r0 + 8) * 132 + cc]     = C[mt][nt][2];
            sc[(r0 + 8) * 132 + cc + 1] = C[mt][nt][3];
        }
    __syncthreads();

    // SiLU(gate)*up -> g_hact hi/lo planes; thread t owns row t (64 outputs)
    {
        size_t orow = (size_t)(base + tid) * Hn + h0;
#pragma unroll
        for (int j = 0; j < 64; j += 4) {
            float v[4];
#pragma unroll
            for (int jj = 0; jj < 4; jj++) {
                float g = sc[tid * 132 + j + jj];
                float u = sc[tid * 132 + 64 + j + jj];
                v[jj] = g / (1.f + __expf(-g)) * u;
            }
            *(uint2*)(g_hact_hi + orow + j) =
                make_uint2(pack_hi(v[0], v[1]), pack_hi(v[2], v[3]));
            *(uint2*)(g_hact_lo + orow + j) =
                make_uint2(pack_lo(v[0], v[1]), pack_lo(v[2], v[3]));
        }
    }
#undef LDGB1
#undef CPA1
#undef STSB1
#undef COMP1
}

// ---------------------------------------------------------------------------
// GEMM2: out[tok, d0+c] += w * sum_h hact[slot,h] * w2[e,h,d0+c]
// CTA 128x128, 4 warps, warp tile 64x64, 3-stage pipeline.
// A = hact planes via cp.async; B = w2 fp32 native [k][n] via LDG+convert,
// ldmatrix.trans read.
// ---------------------------------------------------------------------------
__global__ __launch_bounds__(128, 2) void gemm2_kernel(
    const float* __restrict__ w2,
    float* __restrict__ out) {
    int e = g_tile_expert[blockIdx.x];
    if (e < 0) return;
    int base = g_tile_base[blockIdx.x];
    int d0 = blockIdx.y * 128;

    extern __shared__ char dsm[];
    __shared__ int   s_tok[TILE_M];
    __shared__ float s_w[TILE_M];
    uint32_t raw = smem_u32(dsm);
    uint32_t sb = (raw + 1023u) & ~1023u;
    char* sp = dsm + (sb - raw);

    int tid = threadIdx.x;
    s_tok[tid] = g_slot_token[base + tid];
    s_w[tid]   = g_slot_w[base + tid];
    __syncthreads();

    const int warp = tid >> 5, lane = tid & 31;
    const int wm = warp & 1, wn = warp >> 1;

    // A cp.async: thread t owns row t
    const unsigned short* aHs = g_hact_hi + (size_t)(base + tid) * Hn;
    const unsigned short* aLs = g_hact_lo + (size_t)(base + tid) * Hn;
    const uint32_t aoff = (uint32_t)tid * 128u;

    // B LDG: k-row t>>2 (0..31), d-segment (t&3)*32
    const int kr = tid >> 2, ds = (tid & 3) * 32;
    const float* wP = w2 + ((size_t)e * Hn + kr) * Dn + d0 + ds;
    const uint32_t boff = (uint32_t)kr * 256u + (uint32_t)ds * 2u;

    // ldmatrix lane offsets
    const uint32_t a_m  = (uint32_t)(lane & 15);
    const uint32_t a_kc = (uint32_t)(lane >> 4);
    const uint32_t t_k  = (uint32_t)((lane & 7) | (((lane >> 3) & 1) << 3));
    const uint32_t t_n8 = (uint32_t)(lane >> 4);

    float C[4][8][4];
#pragma unroll
    for (int i = 0; i < 4; i++)
#pragma unroll
        for (int j = 0; j < 8; j++)
#pragma unroll
            for (int k = 0; k < 4; k++) C[i][j][k] = 0.f;

    float4 Br[8];

#define LDGB2(c) do {                                                       \
    const float4* q = (const float4*)(wP + (size_t)(c) * 32 * Dn);          \
    _Pragma("unroll")                                                       \
    for (int i = 0; i < 8; i++) Br[i] = __ldg(q + i);                       \
} while (0)

#define CPA2(c, st) do {                                                    \
    uint32_t Ab = sb + (st) * 32768u;                                       \
    const unsigned short* ah = aHs + (c) * 32;                              \
    const unsigned short* al = aLs + (c) * 32;                              \
    _Pragma("unroll")                                                       \
    for (int g = 0; g < 4; g++) {                                           \
        cpa16(Ab + sw128(aoff + g * 16), ah + g * 8, 16u);                  \
        cpa16(Ab + sw128(aoff + 64 + g * 16), al + g * 8, 16u);             \
    }                                                                       \
    CP_COMMIT();                                                            \
} while (0)

#define STSB2(st) do {                                                      \
    char* Bh = sp + (st) * 32768 + 16384;                                   \
    char* Bl = sp + (st) * 32768 + 24576;                                   \
    _Pragma("unroll")                                                       \
    for (int g = 0; g < 4; g++) {                                           \
        float4 v0 = Br[2 * g], v1 = Br[2 * g + 1];                          \
        uint4 h = make_uint4(pack_hi(v0.x, v0.y), pack_hi(v0.z, v0.w),      \
                             pack_hi(v1.x, v1.y), pack_hi(v1.z, v1.w));     \
        uint4 l = make_uint4(pack_lo(v0.x, v0.y), pack_lo(v0.z, v0.w),      \
                             pack_lo(v1.x, v1.y), pack_lo(v1.z, v1.w));     \
        *(uint4*)(Bh + sw256(boff + g * 16)) = h;                           \
        *(uint4*)(Bl + sw256(boff + g * 16)) = l;                           \
    }                                                                       \
} while (0)

#define COMP2(st) do {                                                      \
    uint32_t Au  = sb + (st) * 32768u;                                      \
    uint32_t Bhu = Au + 16384u;                                             \
    uint32_t Blu = Au + 24576u;                                             \
    _Pragma("unroll")                                                       \
    for (int k16 = 0; k16 < 2; k16++) {                                     \
        uint32_t aH[4][4], aL[4][4];                                        \
        _Pragma("unroll")                                                   \
        for (int mt = 0; mt < 4; mt++) {                                    \
            uint32_t o = (uint32_t)(wm * 64 + mt * 16 + a_m) * 128u + k16 * 32u + a_kc * 16u; \
            ldsm4(aH[mt], Au + sw128(o));                                   \
            ldsm4(aL[mt], Au + sw128(o + 64));                              \
        }                                                                   \
        _Pragma("unroll")                                                   \
        for (int ng = 0; ng < 4; ng++) {                                    \
            uint32_t o = (k16 * 16u + t_k) * 256u                           \
                       + (uint32_t)(wn * 64 + ng * 16) * 2u + t_n8 * 16u;   \
            uint32_t bH[4], bL[4];                                          \
            ldsm4t(bH, Bhu + sw256(o));                                     \
            ldsm4t(bL, Blu + sw256(o));                                     \
            _Pragma("unroll")                                               \
            for (int mt = 0; mt < 4; mt++) {                                \
                mma16816(C[mt][2 * ng],     aH[mt], bH[0], bH[1]);          \
                mma16816(C[mt][2 * ng + 1], aH[mt], bH[2], bH[3]);          \
                mma16816(C[mt][2 * ng],     aL[mt], bH[0], bH[1]);          \
                mma16816(C[mt][2 * ng + 1], aL[mt], bH[2], bH[3]);          \
                mma16816(C[mt][2 * ng],     aH[mt], bL[0], bL[1]);          \
                mma16816(C[mt][2 * ng + 1], aH[mt], bL[2], bL[3]);          \
            }                                                               \
        }                                                                   \
    }                                                                       \
} while (0)

    // 3-stage prologue
    LDGB2(0);
    CPA2(0, 0);
    STSB2(0);
    LDGB2(1);
    CPA2(1, 1);
    for (int c = 0; c < G2_KIT; c++) {
        int st = c % 3;
        if (c + 1 < G2_KIT) CP_WAIT1(); else CP_WAIT0();
        __syncthreads();
        if (c + 2 < G2_KIT) CPA2(c + 2, (c + 2) % 3);
        COMP2(st);
        if (c + 1 < G2_KIT) STSB2((c + 1) % 3);
        if (c + 2 < G2_KIT) LDGB2(c + 2);
    }
    __syncthreads();

    // C -> smem fp32 [128][132]
    float* sc = (float*)sp;
#pragma unroll
    for (int mt = 0; mt < 4; mt++)
#pragma unroll
        for (int nt = 0; nt < 8; nt++) {
            int r0 = wm * 64 + mt * 16 + (lane >> 2);
            int cc = wn * 64 + nt * 8 + (lane & 3) * 2;
            sc[r0 * 132 + cc]       = C[mt][nt][0];
            sc[r0 * 132 + cc + 1]   = C[mt][nt][1];
            sc[(r0 + 8) * 132 + cc]     = C[mt][nt][2];
            sc[(r0 + 8) * 132 + cc + 1] = C[mt][nt][3];
        }
    __syncthreads();

    // weighted accumulate (K=2 commutative adds -> deterministic)
    {
        int tok = s_tok[tid];
        if (tok >= 0) {
            float wgt = s_w[tid];
            float* dst = out + (size_t)tok * Dn + d0;
#pragma unroll 8
            for (int j = 0; j < 128; j++)
                atomicAdd(dst + j, wgt * sc[tid * 132 + j]);
        }
    }
#undef LDGB2
#undef CPA2
#undef STSB2
#undef COMP2
}

// ---------------------------------------------------------------------------
extern "C" void kernel_launch(void* const* d_in, const int* in_sizes, int n_in,
                              void* d_out, int out_size) {
    const float* x   = (const float*)d_in[0];
    const float* wts = (const float*)d_in[1];
    const int*   sel = (const int*)d_in[2];
    const float* w1  = (const float*)d_in[3];
    const float* w2  = (const float*)d_in[4];
    const float* w3  = (const float*)d_in[5];
    float* out = (float*)d_out;

    cudaFuncSetAttribute(gemm1_kernel,
                         cudaFuncAttributeMaxDynamicSharedMemorySize, SMEM_REQ);
    cudaFuncSetAttribute(gemm2_kernel,
                         cudaFuncAttributeMaxDynamicSharedMemorySize, SMEM_REQ);

    route_kernel<<<1, 1024>>>(sel, wts);
    zero_kernel<<<(Tn * Dn) / 256, 256>>>(out);
    splitx_kernel<<<(Tn * Dn) / 1024, 256>>>((const float4*)x, (Tn * Dn) / 4);
    // tile index fastest: all M-tiles of one weight tile run concurrently,
    // weights stream from DRAM once and reuse via L2.
    gemm1_kernel<<<dim3(MAX_TILES, Hn / 64), 128, SMEM_REQ>>>(w1, w3);
    gemm2_kernel<<<dim3(MAX_TILES, Dn / 128), 128, SMEM_REQ>>>(w2, out);
}

// round 8
// speedup vs baseline: 1.0478x; 1.0478x over previous
#include <cuda_runtime.h>
#include <cuda_bf16.h>
#include <cstdint>

// Problem constants
#define Tn 1024
#define Dn 2048
#define Hn 7168
#define En 8
#define Kn 2
#define Pn (Tn * Kn)                   // 2048 (token,k) pairs
#define TILE_M 128
#define MAX_SLOTS (Pn + En * TILE_M)   // 3072
#define MAX_TILES (Pn / TILE_M + En)   // 24

#define G1_KIT (Dn / 32)               // 64 K-chunks of 32
#define G2_KIT (Hn / 32)               // 224 K-chunks of 32

// Dynamic smem: 2 stages x 32KB + slack
#define SMEM_REQ 68608

// Scratch (device globals; no allocation allowed)
__device__ int   g_slot_token[MAX_SLOTS];
__device__ float g_slot_w[MAX_SLOTS];
__device__ int   g_tile_expert[MAX_TILES];
__device__ int   g_tile_base[MAX_TILES];
// bf16 hi/lo planes for the A-side operands (x is tiny; hact produced split)
__device__ __align__(16) unsigned short g_x_hi[(size_t)Tn * Dn];
__device__ __align__(16) unsigned short g_x_lo[(size_t)Tn * Dn];
__device__ __align__(16) unsigned short g_hact_hi[(size_t)MAX_SLOTS * Hn];
__device__ __align__(16) unsigned short g_hact_lo[(size_t)MAX_SLOTS * Hn];

// ---------------------------------------------------------------------------
// Helpers
// ---------------------------------------------------------------------------
__device__ __forceinline__ uint32_t smem_u32(const void* p) {
    uint32_t a;
    asm("{ .reg .u64 t; cvta.to.shared.u64 t, %1; cvt.u32.u64 %0, t; }"
        : "=r"(a) : "l"(p));
    return a;
}

__device__ __forceinline__ uint32_t sw128(uint32_t o) {
    return o ^ (((o >> 7) & 7u) << 4);
}
__device__ __forceinline__ uint32_t sw256(uint32_t o) {
    return o ^ (((o >> 8) & 7u) << 4);
}

__device__ __forceinline__ void cpa16(uint32_t dst, const void* src, uint32_t sz) {
    asm volatile("cp.async.cg.shared.global [%0], [%1], 16, %2;"
                 :: "r"(dst), "l"(src), "r"(sz) : "memory");
}
#define CP_COMMIT() asm volatile("cp.async.commit_group;" ::: "memory")
#define CP_WAIT0()  asm volatile("cp.async.wait_group 0;" ::: "memory")

__device__ __forceinline__ void ldsm4(uint32_t* r, uint32_t a) {
    asm volatile("ldmatrix.sync.aligned.m8n8.x4.shared.b16 {%0,%1,%2,%3}, [%4];"
        : "=r"(r[0]), "=r"(r[1]), "=r"(r[2]), "=r"(r[3]) : "r"(a));
}
__device__ __forceinline__ void ldsm4t(uint32_t* r, uint32_t a) {
    asm volatile("ldmatrix.sync.aligned.m8n8.x4.trans.shared.b16 {%0,%1,%2,%3}, [%4];"
        : "=r"(r[0]), "=r"(r[1]), "=r"(r[2]), "=r"(r[3]) : "r"(a));
}
__device__ __forceinline__ void mma16816(float* c, const uint32_t* a,
                                         uint32_t b0, uint32_t b1) {
    asm volatile(
        "mma.sync.aligned.m16n8k16.row.col.f32.bf16.bf16.f32 "
        "{%0,%1,%2,%3}, {%4,%5,%6,%7}, {%8,%9}, {%0,%1,%2,%3};"
        : "+f"(c[0]), "+f"(c[1]), "+f"(c[2]), "+f"(c[3])
        : "r"(a[0]), "r"(a[1]), "r"(a[2]), "r"(a[3]), "r"(b0), "r"(b1));
}

// bf16 split: hi = truncate(v) (exact in bf16 and fp32), lo = rn(v - hi)
__device__ __forceinline__ uint32_t pack_hi(float a, float b) {
    return (__float_as_uint(a) >> 16) | (__float_as_uint(b) & 0xffff0000u);
}
__device__ __forceinline__ uint32_t pack_lo(float a, float b) {
    float ha = __uint_as_float(__float_as_uint(a) & 0xffff0000u);
    float hb = __uint_as_float(__float_as_uint(b) & 0xffff0000u);
    unsigned short la = __bfloat16_as_ushort(__float2bfloat16(a - ha));
    unsigned short lb = __bfloat16_as_ushort(__float2bfloat16(b - hb));
    return (uint32_t)la | ((uint32_t)lb << 16);
}

// ---------------------------------------------------------------------------
// x split: fp32 -> bf16 hi/lo planes (8 MB, ~8us)
// ---------------------------------------------------------------------------
__global__ void splitx_kernel(const float4* __restrict__ src, int n4) {
    int i = blockIdx.x * blockDim.x + threadIdx.x;
    if (i < n4) {
        float4 v = __ldg(src + i);
        ((uint2*)g_x_hi)[i] = make_uint2(pack_hi(v.x, v.y), pack_hi(v.z, v.w));
        ((uint2*)g_x_lo)[i] = make_uint2(pack_lo(v.x, v.y), pack_lo(v.z, v.w));
    }
}

// ---------------------------------------------------------------------------
// Routing
// ---------------------------------------------------------------------------
__global__ void route_kernel(const int* __restrict__ sel,
                             const float* __restrict__ wts) {
    __shared__ int s_e[Pn];
    __shared__ int s_cnt[En];
    __shared__ int s_base[En];
    int tid = threadIdx.x;

    if (tid < En) s_cnt[tid] = 0;
    __syncthreads();
    for (int i = tid; i < Pn; i += blockDim.x) {
        int e = sel[i];
        s_e[i] = e;
        atomicAdd(&s_cnt[e], 1);
    }
    __syncthreads();
    if (tid == 0) {
        int base = 0, tile = 0;
        for (int e = 0; e < En; e++) {
            s_base[e] = base;
            int padded = ((s_cnt[e] + TILE_M - 1) / TILE_M) * TILE_M;
            for (int m = 0; m < padded; m += TILE_M) {
                g_tile_expert[tile] = e;
                g_tile_base[tile]   = base + m;
                tile++;
            }
            base += padded;
        }
        for (; tile < MAX_TILES; tile++) g_tile_expert[tile] = -1;
    }
    __syncthreads();
    for (int s = tid; s < MAX_SLOTS; s += blockDim.x) g_slot_token[s] = -1;
    __syncthreads();
    for (int i = tid; i < Pn; i += blockDim.x) {
        int e = s_e[i];
        int rank = 0;
        for (int j = 0; j < i; j++) rank += (s_e[j] == e) ? 1 : 0;
        int slot = s_base[e] + rank;
        g_slot_token[slot] = i / Kn;
        g_slot_w[slot]     = wts[i];
    }
}

__global__ void zero_kernel(float* __restrict__ out) {
    int i = blockIdx.x * blockDim.x + threadIdx.x;
    out[i] = 0.0f;
}

// ---------------------------------------------------------------------------
// GEMM1: hact[slot, h0+c] = silu(x.W1^T) * (x.W3^T)
// CTA 128x128 (n 0-63 gate / 64-127 up), BK=32, 4 warps, warp tile 64x64.
// 2-stage pipeline (R6-best). COMP reordered into split-term passes so the
// same accumulator is reused only every 8 mma (breaks HMMA RAW chains).
// ---------------------------------------------------------------------------
__global__ __launch_bounds__(128, 2) void gemm1_kernel(
    const float* __restrict__ w1,
    const float* __restrict__ w3) {
    int e = g_tile_expert[blockIdx.x];
    if (e < 0) return;
    int base = g_tile_base[blockIdx.x];
    int h0 = blockIdx.y * 64;

    extern __shared__ char dsm[];
    __shared__ int s_tok[TILE_M];
    uint32_t raw = smem_u32(dsm);
    uint32_t sb = (raw + 1023u) & ~1023u;
    char* sp = dsm + (sb - raw);

    int tid = threadIdx.x;
    s_tok[tid] = g_slot_token[base + tid];
    __syncthreads();

    const int warp = tid >> 5, lane = tid & 31;
    const int wm = warp & 1, wn = warp >> 1;   // 2m x 2n, warp tile 64x64

    // A cp.async: thread t owns row t (hi 64B + lo 64B per chunk)
    const int tok = s_tok[tid];
    const unsigned short* aHs = g_x_hi + (size_t)(tok < 0 ? 0 : tok) * Dn;
    const unsigned short* aLs = g_x_lo + (size_t)(tok < 0 ? 0 : tok) * Dn;
    const uint32_t asz = (tok >= 0) ? 16u : 0u;
    const uint32_t aoff = (uint32_t)tid * 128u;

    // B LDG: thread t owns weight row t (w1 rows 0-63, w3 rows 64-127)
    const float* bP = (tid < 64)
        ? w1 + ((size_t)e * Hn + h0 + tid) * Dn
        : w3 + ((size_t)e * Hn + h0 + tid - 64) * Dn;
    const uint32_t boff = (uint32_t)tid * 128u;

    // ldmatrix lane offsets
    const uint32_t a_m  = (uint32_t)(lane & 15);
    const uint32_t a_kc = (uint32_t)(lane >> 4);
    const uint32_t b_n  = (uint32_t)((lane & 7) | ((lane >> 4) << 3));
    const uint32_t b_kc = (uint32_t)((lane >> 3) & 1);

    float C[4][8][4];
#pragma unroll
    for (int i = 0; i < 4; i++)
#pragma unroll
        for (int j = 0; j < 8; j++)
#pragma unroll
            for (int k = 0; k < 4; k++) C[i][j][k] = 0.f;

    float4 Br[8];

#define LDGB1(c) do {                                                       \
    const float4* q = (const float4*)(bP + (size_t)(c) * 32);               \
    _Pragma("unroll")                                                       \
    for (int i = 0; i < 8; i++) Br[i] = __ldg(q + i);                       \
} while (0)

#define CPA1(c, st) do {                                                    \
    uint32_t Ab = sb + (st) * 32768u;                                       \
    const unsigned short* ah = aHs + (c) * 32;                              \
    const unsigned short* al = aLs + (c) * 32;                              \
    _Pragma("unroll")                                                       \
    for (int g = 0; g < 4; g++) {                                           \
        cpa16(Ab + sw128(aoff + g * 16), ah + g * 8, asz);                  \
        cpa16(Ab + sw128(aoff + 64 + g * 16), al + g * 8, asz);             \
    }                                                                       \
    CP_COMMIT();                                                            \
} while (0)

#define STSB1(st) do {                                                      \
    char* Bb = sp + (st) * 32768 + 16384;                                   \
    _Pragma("unroll")                                                       \
    for (int g = 0; g < 4; g++) {                                           \
        float4 v0 = Br[2 * g], v1 = Br[2 * g + 1];                          \
        uint4 h = make_uint4(pack_hi(v0.x, v0.y), pack_hi(v0.z, v0.w),      \
                             pack_hi(v1.x, v1.y), pack_hi(v1.z, v1.w));     \
        uint4 l = make_uint4(pack_lo(v0.x, v0.y), pack_lo(v0.z, v0.w),      \
                             pack_lo(v1.x, v1.y), pack_lo(v1.z, v1.w));     \
        *(uint4*)(Bb + sw128(boff + g * 16)) = h;                           \
        *(uint4*)(Bb + sw128(boff + 64 + g * 16)) = l;                      \
    }                                                                       \
} while (0)

// Split-term passes: all-mt HH, all-mt LH, all-mt HL per ng block.
// Same-accumulator reuse distance = 8 mma (was 2).
#define COMP1(st) do {                                                      \
    uint32_t Au = sb + (st) * 32768u;                                       \
    uint32_t Bu = Au + 16384u;                                              \
    _Pragma("unroll")                                                       \
    for (int k16 = 0; k16 < 2; k16++) {                                     \
        uint32_t aH[4][4], aL[4][4];                                        \
        _Pragma("unroll")                                                   \
        for (int mt = 0; mt < 4; mt++) {                                    \
            uint32_t o = (uint32_t)(wm * 64 + mt * 16 + a_m) * 128u + k16 * 32u + a_kc * 16u; \
            ldsm4(aH[mt], Au + sw128(o));                                   \
            ldsm4(aL[mt], Au + sw128(o + 64));                              \
        }                                                                   \
        _Pragma("unroll")                                                   \
        for (int ng = 0; ng < 4; ng++) {                                    \
            uint32_t o = (uint32_t)(wn * 64 + ng * 16 + b_n) * 128u + k16 * 32u + b_kc * 16u; \
            uint32_t bH[4], bL[4];                                          \
            ldsm4(bH, Bu + sw128(o));                                       \
            ldsm4(bL, Bu + sw128(o + 64));                                  \
            _Pragma("unroll")                                               \
            for (int mt = 0; mt < 4; mt++) {                                \
                mma16816(C[mt][2 * ng],     aH[mt], bH[0], bH[1]);          \
                mma16816(C[mt][2 * ng + 1], aH[mt], bH[2], bH[3]);          \
            }                                                               \
            _Pragma("unroll")                                               \
            for (int mt = 0; mt < 4; mt++) {                                \
                mma16816(C[mt][2 * ng],     aL[mt], bH[0], bH[1]);          \
                mma16816(C[mt][2 * ng + 1], aL[mt], bH[2], bH[3]);          \
            }                                                               \
            _Pragma("unroll")                                               \
            for (int mt = 0; mt < 4; mt++) {                                \
                mma16816(C[mt][2 * ng],     aH[mt], bL[0], bL[1]);          \
                mma16816(C[mt][2 * ng + 1], aH[mt], bL[2], bL[3]);          \
            }                                                               \
        }                                                                   \
    }                                                                       \
} while (0)

    LDGB1(0);
    CPA1(0, 0);
    STSB1(0);
    LDGB1(1);
    for (int c = 0; c < G1_KIT; c++) {
        int st = c & 1;
        CP_WAIT0();
        __syncthreads();
        if (c + 1 < G1_KIT) CPA1(c + 1, st ^ 1);
        COMP1(st);
        if (c + 1 < G1_KIT) STSB1(st ^ 1);
        if (c + 2 < G1_KIT) LDGB1(c + 2);
    }
    __syncthreads();

    // C -> smem fp32 [128][132]
    float* sc = (float*)sp;
#pragma unroll
    for (int mt = 0; mt < 4; mt++)
#pragma unroll
        for (int nt = 0; nt < 8; nt++) {
            int r0 = wm * 64 + mt * 16 + (lane >> 2);
            int cc = wn * 64 + nt * 8 + (lane & 3) * 2;
            sc[r0 * 132 + cc]       = C[mt][nt][0];
            sc[r0 * 132 + cc + 1]   = C[mt][nt][1];
            sc[(r0 + 8) * 132 + cc]     = C[mt][nt][2];
            sc[(r0 + 8) * 132 + cc + 1] = C[mt][nt][3];
        }
    __syncthreads();

    // SiLU(gate)*up -> g_hact hi/lo planes; thread t owns row t (64 outputs)
    {
        size_t orow = (size_t)(base + tid) * Hn + h0;
#pragma unroll
        for (int j = 0; j < 64; j += 4) {
            float v[4];
#pragma unroll
            for (int jj = 0; jj < 4; jj++) {
                float g = sc[tid * 132 + j + jj];
                float u = sc[tid * 132 + 64 + j + jj];
                v[jj] = g / (1.f + __expf(-g)) * u;
            }
            *(uint2*)(g_hact_hi + orow + j) =
                make_uint2(pack_hi(v[0], v[1]), pack_hi(v[2], v[3]));
            *(uint2*)(g_hact_lo + orow + j) =
                make_uint2(pack_lo(v[0], v[1]), pack_lo(v[2], v[3]));
        }
    }
#undef LDGB1
#undef CPA1
#undef STSB1
#undef COMP1
}

// ---------------------------------------------------------------------------
// GEMM2: out[tok, d0+c] += w * sum_h hact[slot,h] * w2[e,h,d0+c]
// CTA 128x128, 4 warps, warp tile 64x64, 2-stage pipeline, reordered COMP.
// A = hact planes via cp.async; B = w2 fp32 native [k][n] via LDG+convert,
// ldmatrix.trans read.
// ---------------------------------------------------------------------------
__global__ __launch_bounds__(128, 2) void gemm2_kernel(
    const float* __restrict__ w2,
    float* __restrict__ out) {
    int e = g_tile_expert[blockIdx.x];
    if (e < 0) return;
    int base = g_tile_base[blockIdx.x];
    int d0 = blockIdx.y * 128;

    extern __shared__ char dsm[];
    __shared__ int   s_tok[TILE_M];
    __shared__ float s_w[TILE_M];
    uint32_t raw = smem_u32(dsm);
    uint32_t sb = (raw + 1023u) & ~1023u;
    char* sp = dsm + (sb - raw);

    int tid = threadIdx.x;
    s_tok[tid] = g_slot_token[base + tid];
    s_w[tid]   = g_slot_w[base + tid];
    __syncthreads();

    const int warp = tid >> 5, lane = tid & 31;
    const int wm = warp & 1, wn = warp >> 1;

    // A cp.async: thread t owns row t
    const unsigned short* aHs = g_hact_hi + (size_t)(base + tid) * Hn;
    const unsigned short* aLs = g_hact_lo + (size_t)(base + tid) * Hn;
    const uint32_t aoff = (uint32_t)tid * 128u;

    // B LDG: k-row t>>2 (0..31), d-segment (t&3)*32
    const int kr = tid >> 2, ds = (tid & 3) * 32;
    const float* wP = w2 + ((size_t)e * Hn + kr) * Dn + d0 + ds;
    const uint32_t boff = (uint32_t)kr * 256u + (uint32_t)ds * 2u;

    // ldmatrix lane offsets
    const uint32_t a_m  = (uint32_t)(lane & 15);
    const uint32_t a_kc = (uint32_t)(lane >> 4);
    const uint32_t t_k  = (uint32_t)((lane & 7) | (((lane >> 3) & 1) << 3));
    const uint32_t t_n8 = (uint32_t)(lane >> 4);

    float C[4][8][4];
#pragma unroll
    for (int i = 0; i < 4; i++)
#pragma unroll
        for (int j = 0; j < 8; j++)
#pragma unroll
            for (int k = 0; k < 4; k++) C[i][j][k] = 0.f;

    float4 Br[8];

#define LDGB2(c) do {                                                       \
    const float4* q = (const float4*)(wP + (size_t)(c) * 32 * Dn);          \
    _Pragma("unroll")                                                       \
    for (int i = 0; i < 8; i++) Br[i] = __ldg(q + i);                       \
} while (0)

#define CPA2(c, st) do {                                                    \
    uint32_t Ab = sb + (st) * 32768u;                                       \
    const unsigned short* ah = aHs + (c) * 32;                              \
    const unsigned short* al = aLs + (c) * 32;                              \
    _Pragma("unroll")                                                       \
    for (int g = 0; g < 4; g++) {                                           \
        cpa16(Ab + sw128(aoff + g * 16), ah + g * 8, 16u);                  \
        cpa16(Ab + sw128(aoff + 64 + g * 16), al + g * 8, 16u);             \
    }                                                                       \
    CP_COMMIT();                                                            \
} while (0)

#define STSB2(st) do {                                                      \
    char* Bh = sp + (st) * 32768 + 16384;                                   \
    char* Bl = sp + (st) * 32768 + 24576;                                   \
    _Pragma("unroll")                                                       \
    for (int g = 0; g < 4; g++) {                                           \
        float4 v0 = Br[2 * g], v1 = Br[2 * g + 1];                          \
        uint4 h = make_uint4(pack_hi(v0.x, v0.y), pack_hi(v0.z, v0.w),      \
                             pack_hi(v1.x, v1.y), pack_hi(v1.z, v1.w));     \
        uint4 l = make_uint4(pack_lo(v0.x, v0.y), pack_lo(v0.z, v0.w),      \
                             pack_lo(v1.x, v1.y), pack_lo(v1.z, v1.w));     \
        *(uint4*)(Bh + sw256(boff + g * 16)) = h;                           \
        *(uint4*)(Bl + sw256(boff + g * 16)) = l;                           \
    }                                                                       \
} while (0)

#define COMP2(st) do {                                                      \
    uint32_t Au  = sb + (st) * 32768u;                                      \
    uint32_t Bhu = Au + 16384u;                                             \
    uint32_t Blu = Au + 24576u;                                             \
    _Pragma("unroll")                                                       \
    for (int k16 = 0; k16 < 2; k16++) {                                     \
        uint32_t aH[4][4], aL[4][4];                                        \
        _Pragma("unroll")                                                   \
        for (int mt = 0; mt < 4; mt++) {                                    \
            uint32_t o = (uint32_t)(wm * 64 + mt * 16 + a_m) * 128u + k16 * 32u + a_kc * 16u; \
            ldsm4(aH[mt], Au + sw128(o));                                   \
            ldsm4(aL[mt], Au + sw128(o + 64));                              \
        }                                                                   \
        _Pragma("unroll")                                                   \
        for (int ng = 0; ng < 4; ng++) {                                    \
            uint32_t o = (k16 * 16u + t_k) * 256u                           \
                       + (uint32_t)(wn * 64 + ng * 16) * 2u + t_n8 * 16u;   \
            uint32_t bH[4], bL[4];                                          \
            ldsm4t(bH, Bhu + sw256(o));                                     \
            ldsm4t(bL, Blu + sw256(o));                                     \
            _Pragma("unroll")                                               \
            for (int mt = 0; mt < 4; mt++) {                                \
                mma16816(C[mt][2 * ng],     aH[mt], bH[0], bH[1]);          \
                mma16816(C[mt][2 * ng + 1], aH[mt], bH[2], bH[3]);          \
            }                                                               \
            _Pragma("unroll")                                               \
            for (int mt = 0; mt < 4; mt++) {                                \
                mma16816(C[mt][2 * ng],     aL[mt], bH[0], bH[1]);          \
                mma16816(C[mt][2 * ng + 1], aL[mt], bH[2], bH[3]);          \
            }                                                               \
            _Pragma("unroll")                                               \
            for (int mt = 0; mt < 4; mt++) {                                \
                mma16816(C[mt][2 * ng],     aH[mt], bL[0], bL[1]);          \
                mma16816(C[mt][2 * ng + 1], aH[mt], bL[2], bL[3]);          \
            }                                                               \
        }                                                                   \
    }                                                                       \
} while (0)

    LDGB2(0);
    CPA2(0, 0);
    STSB2(0);
    LDGB2(1);
    for (int c = 0; c < G2_KIT; c++) {
        int st = c & 1;
        CP_WAIT0();
        __syncthreads();
        if (c + 1 < G2_KIT) CPA2(c + 1, st ^ 1);
        COMP2(st);
        if (c + 1 < G2_KIT) STSB2(st ^ 1);
        if (c + 2 < G2_KIT) LDGB2(c + 2);
    }
    __syncthreads();

    // C -> smem fp32 [128][132]
    float* sc = (float*)sp;
#pragma unroll
    for (int mt = 0; mt < 4; mt++)
#pragma unroll
        for (int nt = 0; nt < 8; nt++) {
            int r0 = wm * 64 + mt * 16 + (lane >> 2);
            int cc = wn * 64 + nt * 8 + (lane & 3) * 2;
            sc[r0 * 132 + cc]       = C[mt][nt][0];
            sc[r0 * 132 + cc + 1]   = C[mt][nt][1];
            sc[(r0 + 8) * 132 + cc]     = C[mt][nt][2];
            sc[(r0 + 8) * 132 + cc + 1] = C[mt][nt][3];
        }
    __syncthreads();

    // weighted accumulate (K=2 commutative adds -> deterministic)
    {
        int tok = s_tok[tid];
        if (tok >= 0) {
            float wgt = s_w[tid];
            float* dst = out + (size_t)tok * Dn + d0;
#pragma unroll 8
            for (int j = 0; j < 128; j++)
                atomicAdd(dst + j, wgt * sc[tid * 132 + j]);
        }
    }
#undef LDGB2
#undef CPA2
#undef STSB2
#undef COMP2
}

// ---------------------------------------------------------------------------
extern "C" void kernel_launch(void* const* d_in, const int* in_sizes, int n_in,
                              void* d_out, int out_size) {
    const float* x   = (const float*)d_in[0];
    const float* wts = (const float*)d_in[1];
    const int*   sel = (const int*)d_in[2];
    const float* w1  = (const float*)d_in[3];
    const float* w2  = (const float*)d_in[4];
    const float* w3  = (const float*)d_in[5];
    float* out = (float*)d_out;

    cudaFuncSetAttribute(gemm1_kernel,
                         cudaFuncAttributeMaxDynamicSharedMemorySize, SMEM_REQ);
    cudaFuncSetAttribute(gemm2_kernel,
                         cudaFuncAttributeMaxDynamicSharedMemorySize, SMEM_REQ);

    route_kernel<<<1, 1024>>>(sel, wts);
    zero_kernel<<<(Tn * Dn) / 256, 256>>>(out);
    splitx_kernel<<<(Tn * Dn) / 1024, 256>>>((const float4*)x, (Tn * Dn) / 4);
    // tile index fastest: all M-tiles of one weight tile run concurrently,
    // weights stream from DRAM once and reuse via L2.
    gemm1_kernel<<<dim3(MAX_TILES, Hn / 64), 128, SMEM_REQ>>>(w1, w3);
    gemm2_kernel<<<dim3(MAX_TILES, Dn / 128), 128, SMEM_REQ>>>(w2, out);
}

// round 9
// speedup vs baseline: 1.2372x; 1.1808x over previous
#include <cuda_runtime.h>
#include <cuda_fp16.h>
#include <cstdint>

// Problem constants
#define Tn 1024
#define Dn 2048
#define Hn 7168
#define En 8
#define Kn 2
#define Pn (Tn * Kn)                   // 2048 (token,k) pairs
#define TILE_M 128
#define MAX_SLOTS (Pn + En * TILE_M)   // 3072
#define MAX_TILES (Pn / TILE_M + En)   // 24

#define G1_KIT (Dn / 32)               // 64 K-chunks of 32
#define G2_KIT (Hn / 32)               // 224 K-chunks of 32

// Dynamic smem: 2 stages x 32KB + slack
#define SMEM_REQ 68608

// Scratch (device globals; no allocation allowed)
__device__ int   g_slot_token[MAX_SLOTS];
__device__ float g_slot_w[MAX_SLOTS];
__device__ int   g_tile_expert[MAX_TILES];
__device__ int   g_tile_base[MAX_TILES];
// fp16 hi/lo planes for the A-side operands (near-exact 2-plane repr.)
__device__ __align__(16) unsigned short g_x_hi[(size_t)Tn * Dn];
__device__ __align__(16) unsigned short g_x_lo[(size_t)Tn * Dn];
__device__ __align__(16) unsigned short g_hact_hi[(size_t)MAX_SLOTS * Hn];
__device__ __align__(16) unsigned short g_hact_lo[(size_t)MAX_SLOTS * Hn];

// ---------------------------------------------------------------------------
// Helpers
// ---------------------------------------------------------------------------
__device__ __forceinline__ uint32_t smem_u32(const void* p) {
    uint32_t a;
    asm("{ .reg .u64 t; cvta.to.shared.u64 t, %1; cvt.u32.u64 %0, t; }"
        : "=r"(a) : "l"(p));
    return a;
}

__device__ __forceinline__ uint32_t sw128(uint32_t o) {
    return o ^ (((o >> 7) & 7u) << 4);
}
__device__ __forceinline__ uint32_t sw256(uint32_t o) {
    return o ^ (((o >> 8) & 7u) << 4);
}

__device__ __forceinline__ void cpa16(uint32_t dst, const void* src, uint32_t sz) {
    asm volatile("cp.async.cg.shared.global [%0], [%1], 16, %2;"
                 :: "r"(dst), "l"(src), "r"(sz) : "memory");
}
#define CP_COMMIT() asm volatile("cp.async.commit_group;" ::: "memory")
#define CP_WAIT0()  asm volatile("cp.async.wait_group 0;" ::: "memory")

__device__ __forceinline__ void ldsm4(uint32_t* r, uint32_t a) {
    asm volatile("ldmatrix.sync.aligned.m8n8.x4.shared.b16 {%0,%1,%2,%3}, [%4];"
        : "=r"(r[0]), "=r"(r[1]), "=r"(r[2]), "=r"(r[3]) : "r"(a));
}
__device__ __forceinline__ void ldsm4t(uint32_t* r, uint32_t a) {
    asm volatile("ldmatrix.sync.aligned.m8n8.x4.trans.shared.b16 {%0,%1,%2,%3}, [%4];"
        : "=r"(r[0]), "=r"(r[1]), "=r"(r[2]), "=r"(r[3]) : "r"(a));
}
__device__ __forceinline__ void mma16816h(float* c, const uint32_t* a,
                                          uint32_t b0, uint32_t b1) {
    asm volatile(
        "mma.sync.aligned.m16n8k16.row.col.f32.f16.f16.f32 "
        "{%0,%1,%2,%3}, {%4,%5,%6,%7}, {%8,%9}, {%0,%1,%2,%3};"
        : "+f"(c[0]), "+f"(c[1]), "+f"(c[2]), "+f"(c[3])
        : "r"(a[0]), "r"(a[1]), "r"(a[2]), "r"(a[3]), "r"(b0), "r"(b1));
}

// fp16 helpers: hi = rn(v); lo = rn(v - hi)  (hi+lo represents v to ~2^-22)
__device__ __forceinline__ uint32_t ph_rn(float a, float b) {
    __half2 h = __floats2half2_rn(a, b);
    return *(uint32_t*)&h;
}
__device__ __forceinline__ uint32_t ph_lo(float a, float b) {
    float ra = a - __half2float(__float2half_rn(a));
    float rb = b - __half2float(__float2half_rn(b));
    __half2 h = __floats2half2_rn(ra, rb);
    return *(uint32_t*)&h;
}

// ---------------------------------------------------------------------------
// x split: fp32 -> fp16 hi/lo planes (8 MB, ~8us)
// ---------------------------------------------------------------------------
__global__ void splitx_kernel(const float4* __restrict__ src, int n4) {
    int i = blockIdx.x * blockDim.x + threadIdx.x;
    if (i < n4) {
        float4 v = __ldg(src + i);
        ((uint2*)g_x_hi)[i] = make_uint2(ph_rn(v.x, v.y), ph_rn(v.z, v.w));
        ((uint2*)g_x_lo)[i] = make_uint2(ph_lo(v.x, v.y), ph_lo(v.z, v.w));
    }
}

// ---------------------------------------------------------------------------
// Routing
// ---------------------------------------------------------------------------
__global__ void route_kernel(const int* __restrict__ sel,
                             const float* __restrict__ wts) {
    __shared__ int s_e[Pn];
    __shared__ int s_cnt[En];
    __shared__ int s_base[En];
    int tid = threadIdx.x;

    if (tid < En) s_cnt[tid] = 0;
    __syncthreads();
    for (int i = tid; i < Pn; i += blockDim.x) {
        int e = sel[i];
        s_e[i] = e;
        atomicAdd(&s_cnt[e], 1);
    }
    __syncthreads();
    if (tid == 0) {
        int base = 0, tile = 0;
        for (int e = 0; e < En; e++) {
            s_base[e] = base;
            int padded = ((s_cnt[e] + TILE_M - 1) / TILE_M) * TILE_M;
            for (int m = 0; m < padded; m += TILE_M) {
                g_tile_expert[tile] = e;
                g_tile_base[tile]   = base + m;
                tile++;
            }
            base += padded;
        }
        for (; tile < MAX_TILES; tile++) g_tile_expert[tile] = -1;
    }
    __syncthreads();
    for (int s = tid; s < MAX_SLOTS; s += blockDim.x) g_slot_token[s] = -1;
    __syncthreads();
    for (int i = tid; i < Pn; i += blockDim.x) {
        int e = s_e[i];
        int rank = 0;
        for (int j = 0; j < i; j++) rank += (s_e[j] == e) ? 1 : 0;
        int slot = s_base[e] + rank;
        g_slot_token[slot] = i / Kn;
        g_slot_w[slot]     = wts[i];
    }
}

__global__ void zero_kernel(float* __restrict__ out) {
    int i = blockIdx.x * blockDim.x + threadIdx.x;
    out[i] = 0.0f;
}

// ---------------------------------------------------------------------------
// GEMM1: hact[slot, h0+c] = silu(x.W1^T) * (x.W3^T)
// fp16x2: A 2-plane (exact), B single fp16 plane (error source = w rounding).
// CTA 128x128 (n 0-63 gate / 64-127 up), BK=32, 4 warps, warp tile 64x64.
// 2 mma-terms per K16: aH*b + aL*b  (was 3 with bf16x3).
// ---------------------------------------------------------------------------
__global__ __launch_bounds__(128, 2) void gemm1_kernel(
    const float* __restrict__ w1,
    const float* __restrict__ w3) {
    int e = g_tile_expert[blockIdx.x];
    if (e < 0) return;
    int base = g_tile_base[blockIdx.x];
    int h0 = blockIdx.y * 64;

    extern __shared__ char dsm[];
    __shared__ int s_tok[TILE_M];
    uint32_t raw = smem_u32(dsm);
    uint32_t sb = (raw + 1023u) & ~1023u;
    char* sp = dsm + (sb - raw);

    int tid = threadIdx.x;
    s_tok[tid] = g_slot_token[base + tid];
    __syncthreads();

    const int warp = tid >> 5, lane = tid & 31;
    const int wm = warp & 1, wn = warp >> 1;   // 2m x 2n, warp tile 64x64

    // A cp.async: thread t owns row t (hi 64B + lo 64B per chunk)
    const int tok = s_tok[tid];
    const unsigned short* aHs = g_x_hi + (size_t)(tok < 0 ? 0 : tok) * Dn;
    const unsigned short* aLs = g_x_lo + (size_t)(tok < 0 ? 0 : tok) * Dn;
    const uint32_t asz = (tok >= 0) ? 16u : 0u;
    const uint32_t aoff = (uint32_t)tid * 128u;

    // B LDG: thread t owns weight row t (w1 rows 0-63, w3 rows 64-127)
    const float* bP = (tid < 64)
        ? w1 + ((size_t)e * Hn + h0 + tid) * Dn
        : w3 + ((size_t)e * Hn + h0 + tid - 64) * Dn;
    const uint32_t boff = (uint32_t)tid * 128u;   // row stride stays 128B

    // ldmatrix lane offsets
    const uint32_t a_m  = (uint32_t)(lane & 15);
    const uint32_t a_kc = (uint32_t)(lane >> 4);
    const uint32_t b_n  = (uint32_t)((lane & 7) | ((lane >> 4) << 3));
    const uint32_t b_kc = (uint32_t)((lane >> 3) & 1);

    float C[4][8][4];
#pragma unroll
    for (int i = 0; i < 4; i++)
#pragma unroll
        for (int j = 0; j < 8; j++)
#pragma unroll
            for (int k = 0; k < 4; k++) C[i][j][k] = 0.f;

    float4 Br[8];

#define LDGB1(c) do {                                                       \
    const float4* q = (const float4*)(bP + (size_t)(c) * 32);               \
    _Pragma("unroll")                                                       \
    for (int i = 0; i < 8; i++) Br[i] = __ldg(q + i);                       \
} while (0)

#define CPA1(c, st) do {                                                    \
    uint32_t Ab = sb + (st) * 32768u;                                       \
    const unsigned short* ah = aHs + (c) * 32;                              \
    const unsigned short* al = aLs + (c) * 32;                              \
    _Pragma("unroll")                                                       \
    for (int g = 0; g < 4; g++) {                                           \
        cpa16(Ab + sw128(aoff + g * 16), ah + g * 8, asz);                  \
        cpa16(Ab + sw128(aoff + 64 + g * 16), al + g * 8, asz);             \
    }                                                                       \
    CP_COMMIT();                                                            \
} while (0)

// B: single fp16 plane -> first 64B of each 128B row
#define STSB1(st) do {                                                      \
    char* Bb = sp + (st) * 32768 + 16384;                                   \
    _Pragma("unroll")                                                       \
    for (int g = 0; g < 4; g++) {                                           \
        float4 v0 = Br[2 * g], v1 = Br[2 * g + 1];                          \
        uint4 h = make_uint4(ph_rn(v0.x, v0.y), ph_rn(v0.z, v0.w),          \
                             ph_rn(v1.x, v1.y), ph_rn(v1.z, v1.w));         \
        *(uint4*)(Bb + sw128(boff + g * 16)) = h;                           \
    }                                                                       \
} while (0)

#define COMP1(st) do {                                                      \
    uint32_t Au = sb + (st) * 32768u;                                       \
    uint32_t Bu = Au + 16384u;                                              \
    _Pragma("unroll")                                                       \
    for (int k16 = 0; k16 < 2; k16++) {                                     \
        uint32_t aH[4][4], aL[4][4];                                        \
        _Pragma("unroll")                                                   \
        for (int mt = 0; mt < 4; mt++) {                                    \
            uint32_t o = (uint32_t)(wm * 64 + mt * 16 + a_m) * 128u + k16 * 32u + a_kc * 16u; \
            ldsm4(aH[mt], Au + sw128(o));                                   \
            ldsm4(aL[mt], Au + sw128(o + 64));                              \
        }                                                                   \
        _Pragma("unroll")                                                   \
        for (int ng = 0; ng < 4; ng++) {                                    \
            uint32_t o = (uint32_t)(wn * 64 + ng * 16 + b_n) * 128u + k16 * 32u + b_kc * 16u; \
            uint32_t bH[4];                                                 \
            ldsm4(bH, Bu + sw128(o));                                       \
            _Pragma("unroll")                                               \
            for (int mt = 0; mt < 4; mt++) {                                \
                mma16816h(C[mt][2 * ng],     aH[mt], bH[0], bH[1]);         \
                mma16816h(C[mt][2 * ng + 1], aH[mt], bH[2], bH[3]);         \
            }                                                               \
            _Pragma("unroll")                                               \
            for (int mt = 0; mt < 4; mt++) {                                \
                mma16816h(C[mt][2 * ng],     aL[mt], bH[0], bH[1]);         \
                mma16816h(C[mt][2 * ng + 1], aL[mt], bH[2], bH[3]);         \
            }                                                               \
        }                                                                   \
    }                                                                       \
} while (0)

    LDGB1(0);
    CPA1(0, 0);
    STSB1(0);
    LDGB1(1);
    for (int c = 0; c < G1_KIT; c++) {
        int st = c & 1;
        CP_WAIT0();
        __syncthreads();
        if (c + 1 < G1_KIT) CPA1(c + 1, st ^ 1);
        COMP1(st);
        if (c + 1 < G1_KIT) STSB1(st ^ 1);
        if (c + 2 < G1_KIT) LDGB1(c + 2);
    }
    __syncthreads();

    // C -> smem fp32 [128][132]
    float* sc = (float*)sp;
#pragma unroll
    for (int mt = 0; mt < 4; mt++)
#pragma unroll
        for (int nt = 0; nt < 8; nt++) {
            int r0 = wm * 64 + mt * 16 + (lane >> 2);
            int cc = wn * 64 + nt * 8 + (lane & 3) * 2;
            sc[r0 * 132 + cc]       = C[mt][nt][0];
            sc[r0 * 132 + cc + 1]   = C[mt][nt][1];
            sc[(r0 + 8) * 132 + cc]     = C[mt][nt][2];
            sc[(r0 + 8) * 132 + cc + 1] = C[mt][nt][3];
        }
    __syncthreads();

    // SiLU(gate)*up -> g_hact fp16 hi/lo planes; thread t owns row t
    {
        size_t orow = (size_t)(base + tid) * Hn + h0;
#pragma unroll
        for (int j = 0; j < 64; j += 4) {
            float v[4];
#pragma unroll
            for (int jj = 0; jj < 4; jj++) {
                float g = sc[tid * 132 + j + jj];
                float u = sc[tid * 132 + 64 + j + jj];
                v[jj] = g / (1.f + __expf(-g)) * u;
            }
            *(uint2*)(g_hact_hi + orow + j) =
                make_uint2(ph_rn(v[0], v[1]), ph_rn(v[2], v[3]));
            *(uint2*)(g_hact_lo + orow + j) =
                make_uint2(ph_lo(v[0], v[1]), ph_lo(v[2], v[3]));
        }
    }
#undef LDGB1
#undef CPA1
#undef STSB1
#undef COMP1
}

// ---------------------------------------------------------------------------
// GEMM2: out[tok, d0+c] += w * sum_h hact[slot,h] * w2[e,h,d0+c]
// fp16x2: A = hact 2-plane (exact), B = w2 single fp16 plane (trans ldsm).
// CTA 128x128, 4 warps, warp tile 64x64, 2-stage pipeline, 2 mma-terms.
// ---------------------------------------------------------------------------
__global__ __launch_bounds__(128, 2) void gemm2_kernel(
    const float* __restrict__ w2,
    float* __restrict__ out) {
    int e = g_tile_expert[blockIdx.x];
    if (e < 0) return;
    int base = g_tile_base[blockIdx.x];
    int d0 = blockIdx.y * 128;

    extern __shared__ char dsm[];
    __shared__ int   s_tok[TILE_M];
    __shared__ float s_w[TILE_M];
    uint32_t raw = smem_u32(dsm);
    uint32_t sb = (raw + 1023u) & ~1023u;
    char* sp = dsm + (sb - raw);

    int tid = threadIdx.x;
    s_tok[tid] = g_slot_token[base + tid];
    s_w[tid]   = g_slot_w[base + tid];
    __syncthreads();

    const int warp = tid >> 5, lane = tid & 31;
    const int wm = warp & 1, wn = warp >> 1;

    // A cp.async: thread t owns row t
    const unsigned short* aHs = g_hact_hi + (size_t)(base + tid) * Hn;
    const unsigned short* aLs = g_hact_lo + (size_t)(base + tid) * Hn;
    const uint32_t aoff = (uint32_t)tid * 128u;

    // B LDG: k-row t>>2 (0..31), d-segment (t&3)*32
    const int kr = tid >> 2, ds = (tid & 3) * 32;
    const float* wP = w2 + ((size_t)e * Hn + kr) * Dn + d0 + ds;
    const uint32_t boff = (uint32_t)kr * 256u + (uint32_t)ds * 2u;

    // ldmatrix lane offsets
    const uint32_t a_m  = (uint32_t)(lane & 15);
    const uint32_t a_kc = (uint32_t)(lane >> 4);
    const uint32_t t_k  = (uint32_t)((lane & 7) | (((lane >> 3) & 1) << 3));
    const uint32_t t_n8 = (uint32_t)(lane >> 4);

    float C[4][8][4];
#pragma unroll
    for (int i = 0; i < 4; i++)
#pragma unroll
        for (int j = 0; j < 8; j++)
#pragma unroll
            for (int k = 0; k < 4; k++) C[i][j][k] = 0.f;

    float4 Br[8];

#define LDGB2(c) do {                                                       \
    const float4* q = (const float4*)(wP + (size_t)(c) * 32 * Dn);          \
    _Pragma("unroll")                                                       \
    for (int i = 0; i < 8; i++) Br[i] = __ldg(q + i);                       \
} while (0)

#define CPA2(c, st) do {                                                    \
    uint32_t Ab = sb + (st) * 32768u;                                       \
    const unsigned short* ah = aHs + (c) * 32;                              \
    const unsigned short* al = aLs + (c) * 32;                              \
    _Pragma("unroll")                                                       \
    for (int g = 0; g < 4; g++) {                                           \
        cpa16(Ab + sw128(aoff + g * 16), ah + g * 8, 16u);                  \
        cpa16(Ab + sw128(aoff + 64 + g * 16), al + g * 8, 16u);             \
    }                                                                       \
    CP_COMMIT();                                                            \
} while (0)

#define STSB2(st) do {                                                      \
    char* Bh = sp + (st) * 32768 + 16384;                                   \
    _Pragma("unroll")                                                       \
    for (int g = 0; g < 4; g++) {                                           \
        float4 v0 = Br[2 * g], v1 = Br[2 * g + 1];                          \
        uint4 h = make_uint4(ph_rn(v0.x, v0.y), ph_rn(v0.z, v0.w),          \
                             ph_rn(v1.x, v1.y), ph_rn(v1.z, v1.w));         \
        *(uint4*)(Bh + sw256(boff + g * 16)) = h;                           \
    }                                                                       \
} while (0)

#define COMP2(st) do {                                                      \
    uint32_t Au  = sb + (st) * 32768u;                                      \
    uint32_t Bhu = Au + 16384u;                                             \
    _Pragma("unroll")                                                       \
    for (int k16 = 0; k16 < 2; k16++) {                                     \
        uint32_t aH[4][4], aL[4][4];                                        \
        _Pragma("unroll")                                                   \
        for (int mt = 0; mt < 4; mt++) {                                    \
            uint32_t o = (uint32_t)(wm * 64 + mt * 16 + a_m) * 128u + k16 * 32u + a_kc * 16u; \
            ldsm4(aH[mt], Au + sw128(o));                                   \
            ldsm4(aL[mt], Au + sw128(o + 64));                              \
        }                                                                   \
        _Pragma("unroll")                                                   \
        for (int ng = 0; ng < 4; ng++) {                                    \
            uint32_t o = (k16 * 16u + t_k) * 256u                           \
                       + (uint32_t)(wn * 64 + ng * 16) * 2u + t_n8 * 16u;   \
            uint32_t bH[4];                                                 \
            ldsm4t(bH, Bhu + sw256(o));                                     \
            _Pragma("unroll")                                               \
            for (int mt = 0; mt < 4; mt++) {                                \
                mma16816h(C[mt][2 * ng],     aH[mt], bH[0], bH[1]);         \
                mma16816h(C[mt][2 * ng + 1], aH[mt], bH[2], bH[3]);         \
            }                                                               \
            _Pragma("unroll")                                               \
            for (int mt = 0; mt < 4; mt++) {                                \
                mma16816h(C[mt][2 * ng],     aL[mt], bH[0], bH[1]);         \
                mma16816h(C[mt][2 * ng + 1], aL[mt], bH[2], bH[3]);         \
            }                                                               \
        }                                                                   \
    }                                                                       \
} while (0)

    LDGB2(0);
    CPA2(0, 0);
    STSB2(0);
    LDGB2(1);
    for (int c = 0; c < G2_KIT; c++) {
        int st = c & 1;
        CP_WAIT0();
        __syncthreads();
        if (c + 1 < G2_KIT) CPA2(c + 1, st ^ 1);
        COMP2(st);
        if (c + 1 < G2_KIT) STSB2(st ^ 1);
        if (c + 2 < G2_KIT) LDGB2(c + 2);
    }
    __syncthreads();

    // C -> smem fp32 [128][132]
    float* sc = (float*)sp;
#pragma unroll
    for (int mt = 0; mt < 4; mt++)
#pragma unroll
        for (int nt = 0; nt < 8; nt++) {
            int r0 = wm * 64 + mt * 16 + (lane >> 2);
            int cc = wn * 64 + nt * 8 + (lane & 3) * 2;
            sc[r0 * 132 + cc]       = C[mt][nt][0];
            sc[r0 * 132 + cc + 1]   = C[mt][nt][1];
            sc[(r0 + 8) * 132 + cc]     = C[mt][nt][2];
            sc[(r0 + 8) * 132 + cc + 1] = C[mt][nt][3];
        }
    __syncthreads();

    // weighted accumulate (K=2 commutative adds -> deterministic)
    {
        int tok = s_tok[tid];
        if (tok >= 0) {
            float wgt = s_w[tid];
            float* dst = out + (size_t)tok * Dn + d0;
#pragma unroll 8
            for (int j = 0; j < 128; j++)
                atomicAdd(dst + j, wgt * sc[tid * 132 + j]);
        }
    }
#undef LDGB2
#undef CPA2
#undef STSB2
#undef COMP2
}

// ---------------------------------------------------------------------------
extern "C" void kernel_launch(void* const* d_in, const int* in_sizes, int n_in,
                              void* d_out, int out_size) {
    const float* x   = (const float*)d_in[0];
    const float* wts = (const float*)d_in[1];
    const int*   sel = (const int*)d_in[2];
    const float* w1  = (const float*)d_in[3];
    const float* w2  = (const float*)d_in[4];
    const float* w3  = (const float*)d_in[5];
    float* out = (float*)d_out;

    cudaFuncSetAttribute(gemm1_kernel,
                         cudaFuncAttributeMaxDynamicSharedMemorySize, SMEM_REQ);
    cudaFuncSetAttribute(gemm2_kernel,
                         cudaFuncAttributeMaxDynamicSharedMemorySize, SMEM_REQ);

    route_kernel<<<1, 1024>>>(sel, wts);
    zero_kernel<<<(Tn * Dn) / 256, 256>>>(out);
    splitx_kernel<<<(Tn * Dn) / 1024, 256>>>((const float4*)x, (Tn * Dn) / 4);
    // tile index fastest: all M-tiles of one weight tile run concurrently,
    // weights stream from DRAM once and reuse via L2.
    gemm1_kernel<<<dim3(MAX_TILES, Hn / 64), 128, SMEM_REQ>>>(w1, w3);
    gemm2_kernel<<<dim3(MAX_TILES, Dn / 128), 128, SMEM_REQ>>>(w2, out);
}

// round 10
// speedup vs baseline: 1.7677x; 1.4288x over previous
#include <cuda_runtime.h>
#include <cuda_fp16.h>
#include <cstdint>

// Problem constants
#define Tn 1024
#define Dn 2048
#define Hn 7168
#define En 8
#define Kn 2
#define Pn (Tn * Kn)                   // 2048 (token,k) pairs
#define TILE_M 128
#define MAX_SLOTS (Pn + En * TILE_M)   // 3072
#define MAX_TILES (Pn / TILE_M + En)   // 24

#define G1_KIT (Dn / 32)               // 64 K-chunks of 32
#define G2_KIT (Hn / 32)               // 224 K-chunks of 32

// Dynamic smem: 2 stages x 32KB + slack (epilogue reuses as 128x132 fp32)
#define SMEM_REQ 68608

// Scratch (device globals; no allocation allowed)
__device__ int   g_slot_token[MAX_SLOTS];
__device__ float g_slot_w[MAX_SLOTS];
__device__ int   g_tile_expert[MAX_TILES];
__device__ int   g_tile_base[MAX_TILES];
// single fp16 plane for the A-side operands
__device__ __align__(16) unsigned short g_x_h[(size_t)Tn * Dn];
__device__ __align__(16) unsigned short g_hact_h[(size_t)MAX_SLOTS * Hn];

// ---------------------------------------------------------------------------
// Helpers
// ---------------------------------------------------------------------------
__device__ __forceinline__ uint32_t smem_u32(const void* p) {
    uint32_t a;
    asm("{ .reg .u64 t; cvta.to.shared.u64 t, %1; cvt.u32.u64 %0, t; }"
        : "=r"(a) : "l"(p));
    return a;
}

__device__ __forceinline__ uint32_t sw128(uint32_t o) {
    return o ^ (((o >> 7) & 7u) << 4);
}
__device__ __forceinline__ uint32_t sw256(uint32_t o) {
    return o ^ (((o >> 8) & 7u) << 4);
}

__device__ __forceinline__ void cpa16(uint32_t dst, const void* src, uint32_t sz) {
    asm volatile("cp.async.cg.shared.global [%0], [%1], 16, %2;"
                 :: "r"(dst), "l"(src), "r"(sz) : "memory");
}
#define CP_COMMIT() asm volatile("cp.async.commit_group;" ::: "memory")
#define CP_WAIT0()  asm volatile("cp.async.wait_group 0;" ::: "memory")

__device__ __forceinline__ void ldsm4(uint32_t* r, uint32_t a) {
    asm volatile("ldmatrix.sync.aligned.m8n8.x4.shared.b16 {%0,%1,%2,%3}, [%4];"
        : "=r"(r[0]), "=r"(r[1]), "=r"(r[2]), "=r"(r[3]) : "r"(a));
}
__device__ __forceinline__ void ldsm4t(uint32_t* r, uint32_t a) {
    asm volatile("ldmatrix.sync.aligned.m8n8.x4.trans.shared.b16 {%0,%1,%2,%3}, [%4];"
        : "=r"(r[0]), "=r"(r[1]), "=r"(r[2]), "=r"(r[3]) : "r"(a));
}
__device__ __forceinline__ void mma16816h(float* c, const uint32_t* a,
                                          uint32_t b0, uint32_t b1) {
    asm volatile(
        "mma.sync.aligned.m16n8k16.row.col.f32.f16.f16.f32 "
        "{%0,%1,%2,%3}, {%4,%5,%6,%7}, {%8,%9}, {%0,%1,%2,%3};"
        : "+f"(c[0]), "+f"(c[1]), "+f"(c[2]), "+f"(c[3])
        : "r"(a[0]), "r"(a[1]), "r"(a[2]), "r"(a[3]), "r"(b0), "r"(b1));
}

__device__ __forceinline__ uint32_t ph_rn(float a, float b) {
    __half2 h = __floats2half2_rn(a, b);
    return *(uint32_t*)&h;
}

// ---------------------------------------------------------------------------
// x convert: fp32 -> fp16 plane (4 MB, ~4us)
// ---------------------------------------------------------------------------
__global__ void splitx_kernel(const float4* __restrict__ src, int n4) {
    int i = blockIdx.x * blockDim.x + threadIdx.x;
    if (i < n4) {
        float4 v = __ldg(src + i);
        ((uint2*)g_x_h)[i] = make_uint2(ph_rn(v.x, v.y), ph_rn(v.z, v.w));
    }
}

// ---------------------------------------------------------------------------
// Routing
// ---------------------------------------------------------------------------
__global__ void route_kernel(const int* __restrict__ sel,
                             const float* __restrict__ wts) {
    __shared__ int s_e[Pn];
    __shared__ int s_cnt[En];
    __shared__ int s_base[En];
    int tid = threadIdx.x;

    if (tid < En) s_cnt[tid] = 0;
    __syncthreads();
    for (int i = tid; i < Pn; i += blockDim.x) {
        int e = sel[i];
        s_e[i] = e;
        atomicAdd(&s_cnt[e], 1);
    }
    __syncthreads();
    if (tid == 0) {
        int base = 0, tile = 0;
        for (int e = 0; e < En; e++) {
            s_base[e] = base;
            int padded = ((s_cnt[e] + TILE_M - 1) / TILE_M) * TILE_M;
            for (int m = 0; m < padded; m += TILE_M) {
                g_tile_expert[tile] = e;
                g_tile_base[tile]   = base + m;
                tile++;
            }
            base += padded;
        }
        for (; tile < MAX_TILES; tile++) g_tile_expert[tile] = -1;
    }
    __syncthreads();
    for (int s = tid; s < MAX_SLOTS; s += blockDim.x) g_slot_token[s] = -1;
    __syncthreads();
    for (int i = tid; i < Pn; i += blockDim.x) {
        int e = s_e[i];
        int rank = 0;
        for (int j = 0; j < i; j++) rank += (s_e[j] == e) ? 1 : 0;
        int slot = s_base[e] + rank;
        g_slot_token[slot] = i / Kn;
        g_slot_w[slot]     = wts[i];
    }
}

__global__ void zero_kernel(float* __restrict__ out) {
    int i = blockIdx.x * blockDim.x + threadIdx.x;
    out[i] = 0.0f;
}

// ---------------------------------------------------------------------------
// GEMM1: hact[slot, h0+c] = silu(x.W1^T) * (x.W3^T)
// Plain fp16 x fp16 -> fp32 accum. CTA 128x128 (n 0-63 gate / 64-127 up),
// BK=32, 4 warps, warp tile 64x64, 2-stage pipeline. A single plane.
// ---------------------------------------------------------------------------
__global__ __launch_bounds__(128, 2) void gemm1_kernel(
    const float* __restrict__ w1,
    const float* __restrict__ w3) {
    int e = g_tile_expert[blockIdx.x];
    if (e < 0) return;
    int base = g_tile_base[blockIdx.x];
    int h0 = blockIdx.y * 64;

    extern __shared__ char dsm[];
    __shared__ int s_tok[TILE_M];
    uint32_t raw = smem_u32(dsm);
    uint32_t sb = (raw + 1023u) & ~1023u;
    char* sp = dsm + (sb - raw);

    int tid = threadIdx.x;
    s_tok[tid] = g_slot_token[base + tid];
    __syncthreads();

    const int warp = tid >> 5, lane = tid & 31;
    const int wm = warp & 1, wn = warp >> 1;   // 2m x 2n, warp tile 64x64

    // A cp.async: thread t owns row t (64B per chunk, first half of 128B row)
    const int tok = s_tok[tid];
    const unsigned short* aHs = g_x_h + (size_t)(tok < 0 ? 0 : tok) * Dn;
    const uint32_t asz = (tok >= 0) ? 16u : 0u;
    const uint32_t aoff = (uint32_t)tid * 128u;

    // B LDG: thread t owns weight row t (w1 rows 0-63, w3 rows 64-127)
    const float* bP = (tid < 64)
        ? w1 + ((size_t)e * Hn + h0 + tid) * Dn
        : w3 + ((size_t)e * Hn + h0 + tid - 64) * Dn;
    const uint32_t boff = (uint32_t)tid * 128u;

    // ldmatrix lane offsets
    const uint32_t a_m  = (uint32_t)(lane & 15);
    const uint32_t a_kc = (uint32_t)(lane >> 4);
    const uint32_t b_n  = (uint32_t)((lane & 7) | ((lane >> 4) << 3));
    const uint32_t b_kc = (uint32_t)((lane >> 3) & 1);

    float C[4][8][4];
#pragma unroll
    for (int i = 0; i < 4; i++)
#pragma unroll
        for (int j = 0; j < 8; j++)
#pragma unroll
            for (int k = 0; k < 4; k++) C[i][j][k] = 0.f;

    float4 Br[8];

#define LDGB1(c) do {                                                       \
    const float4* q = (const float4*)(bP + (size_t)(c) * 32);               \
    _Pragma("unroll")                                                       \
    for (int i = 0; i < 8; i++) Br[i] = __ldg(q + i);                       \
} while (0)

#define CPA1(c, st) do {                                                    \
    uint32_t Ab = sb + (st) * 32768u;                                       \
    const unsigned short* ah = aHs + (c) * 32;                              \
    _Pragma("unroll")                                                       \
    for (int g = 0; g < 4; g++)                                             \
        cpa16(Ab + sw128(aoff + g * 16), ah + g * 8, asz);                  \
    CP_COMMIT();                                                            \
} while (0)

#define STSB1(st) do {                                                      \
    char* Bb = sp + (st) * 32768 + 16384;                                   \
    _Pragma("unroll")                                                       \
    for (int g = 0; g < 4; g++) {                                           \
        float4 v0 = Br[2 * g], v1 = Br[2 * g + 1];                          \
        uint4 h = make_uint4(ph_rn(v0.x, v0.y), ph_rn(v0.z, v0.w),          \
                             ph_rn(v1.x, v1.y), ph_rn(v1.z, v1.w));         \
        *(uint4*)(Bb + sw128(boff + g * 16)) = h;                           \
    }                                                                       \
} while (0)

#define COMP1(st) do {                                                      \
    uint32_t Au = sb + (st) * 32768u;                                       \
    uint32_t Bu = Au + 16384u;                                              \
    _Pragma("unroll")                                                       \
    for (int k16 = 0; k16 < 2; k16++) {                                     \
        uint32_t aH[4][4];                                                  \
        _Pragma("unroll")                                                   \
        for (int mt = 0; mt < 4; mt++) {                                    \
            uint32_t o = (uint32_t)(wm * 64 + mt * 16 + a_m) * 128u + k16 * 32u + a_kc * 16u; \
            ldsm4(aH[mt], Au + sw128(o));                                   \
        }                                                                   \
        _Pragma("unroll")                                                   \
        for (int ng = 0; ng < 4; ng++) {                                    \
            uint32_t o = (uint32_t)(wn * 64 + ng * 16 + b_n) * 128u + k16 * 32u + b_kc * 16u; \
            uint32_t bH[4];                                                 \
            ldsm4(bH, Bu + sw128(o));                                       \
            _Pragma("unroll")                                               \
            for (int mt = 0; mt < 4; mt++) {                                \
                mma16816h(C[mt][2 * ng],     aH[mt], bH[0], bH[1]);         \
                mma16816h(C[mt][2 * ng + 1], aH[mt], bH[2], bH[3]);         \
            }                                                               \
        }                                                                   \
    }                                                                       \
} while (0)

    LDGB1(0);
    CPA1(0, 0);
    STSB1(0);
    LDGB1(1);
    for (int c = 0; c < G1_KIT; c++) {
        int st = c & 1;
        CP_WAIT0();
        __syncthreads();
        if (c + 1 < G1_KIT) CPA1(c + 1, st ^ 1);
        COMP1(st);
        if (c + 1 < G1_KIT) STSB1(st ^ 1);
        if (c + 2 < G1_KIT) LDGB1(c + 2);
    }
    __syncthreads();

    // C -> smem fp32 [128][132]
    float* sc = (float*)sp;
#pragma unroll
    for (int mt = 0; mt < 4; mt++)
#pragma unroll
        for (int nt = 0; nt < 8; nt++) {
            int r0 = wm * 64 + mt * 16 + (lane >> 2);
            int cc = wn * 64 + nt * 8 + (lane & 3) * 2;
            sc[r0 * 132 + cc]       = C[mt][nt][0];
            sc[r0 * 132 + cc + 1]   = C[mt][nt][1];
            sc[(r0 + 8) * 132 + cc]     = C[mt][nt][2];
            sc[(r0 + 8) * 132 + cc + 1] = C[mt][nt][3];
        }
    __syncthreads();

    // SiLU(gate)*up -> g_hact fp16 plane; thread t owns row t (64 outputs)
    {
        size_t orow = (size_t)(base + tid) * Hn + h0;
#pragma unroll
        for (int j = 0; j < 64; j += 4) {
            float v[4];
#pragma unroll
            for (int jj = 0; jj < 4; jj++) {
                float g = sc[tid * 132 + j + jj];
                float u = sc[tid * 132 + 64 + j + jj];
                v[jj] = g / (1.f + __expf(-g)) * u;
            }
            *(uint2*)(g_hact_h + orow + j) =
                make_uint2(ph_rn(v[0], v[1]), ph_rn(v[2], v[3]));
        }
    }
#undef LDGB1
#undef CPA1
#undef STSB1
#undef COMP1
}

// ---------------------------------------------------------------------------
// GEMM2: out[tok, d0+c] += w * sum_h hact[slot,h] * w2[e,h,d0+c]
// Plain fp16. CTA 128x128, 4 warps, warp tile 64x64, 2-stage pipeline.
// A = hact plane via cp.async; B = w2 fp32 native [k][n] via LDG+convert,
// ldmatrix.trans read.
// ---------------------------------------------------------------------------
__global__ __launch_bounds__(128, 2) void gemm2_kernel(
    const float* __restrict__ w2,
    float* __restrict__ out) {
    int e = g_tile_expert[blockIdx.x];
    if (e < 0) return;
    int base = g_tile_base[blockIdx.x];
    int d0 = blockIdx.y * 128;

    extern __shared__ char dsm[];
    __shared__ int   s_tok[TILE_M];
    __shared__ float s_w[TILE_M];
    uint32_t raw = smem_u32(dsm);
    uint32_t sb = (raw + 1023u) & ~1023u;
    char* sp = dsm + (sb - raw);

    int tid = threadIdx.x;
    s_tok[tid] = g_slot_token[base + tid];
    s_w[tid]   = g_slot_w[base + tid];
    __syncthreads();

    const int warp = tid >> 5, lane = tid & 31;
    const int wm = warp & 1, wn = warp >> 1;

    // A cp.async: thread t owns row t
    const unsigned short* aHs = g_hact_h + (size_t)(base + tid) * Hn;
    const uint32_t aoff = (uint32_t)tid * 128u;

    // B LDG: k-row t>>2 (0..31), d-segment (t&3)*32
    const int kr = tid >> 2, ds = (tid & 3) * 32;
    const float* wP = w2 + ((size_t)e * Hn + kr) * Dn + d0 + ds;
    const uint32_t boff = (uint32_t)kr * 256u + (uint32_t)ds * 2u;

    // ldmatrix lane offsets
    const uint32_t a_m  = (uint32_t)(lane & 15);
    const uint32_t a_kc = (uint32_t)(lane >> 4);
    const uint32_t t_k  = (uint32_t)((lane & 7) | (((lane >> 3) & 1) << 3));
    const uint32_t t_n8 = (uint32_t)(lane >> 4);

    float C[4][8][4];
#pragma unroll
    for (int i = 0; i < 4; i++)
#pragma unroll
        for (int j = 0; j < 8; j++)
#pragma unroll
            for (int k = 0; k < 4; k++) C[i][j][k] = 0.f;

    float4 Br[8];

#define LDGB2(c) do {                                                       \
    const float4* q = (const float4*)(wP + (size_t)(c) * 32 * Dn);          \
    _Pragma("unroll")                                                       \
    for (int i = 0; i < 8; i++) Br[i] = __ldg(q + i);                       \
} while (0)

#define CPA2(c, st) do {                                                    \
    uint32_t Ab = sb + (st) * 32768u;                                       \
    const unsigned short* ah = aHs + (c) * 32;                              \
    _Pragma("unroll")                                                       \
    for (int g = 0; g < 4; g++)                                             \
        cpa16(Ab + sw128(aoff + g * 16), ah + g * 8, 16u);                  \
    CP_COMMIT();                                                            \
} while (0)

#define STSB2(st) do {                                                      \
    char* Bh = sp + (st) * 32768 + 16384;                                   \
    _Pragma("unroll")                                                       \
    for (int g = 0; g < 4; g++) {                                           \
        float4 v0 = Br[2 * g], v1 = Br[2 * g + 1];                          \
        uint4 h = make_uint4(ph_rn(v0.x, v0.y), ph_rn(v0.z, v0.w),          \
                             ph_rn(v1.x, v1.y), ph_rn(v1.z, v1.w));         \
        *(uint4*)(Bh + sw256(boff + g * 16)) = h;                           \
    }                                                                       \
} while (0)

#define COMP2(st) do {                                                      \
    uint32_t Au  = sb + (st) * 32768u;                                      \
    uint32_t Bhu = Au + 16384u;                                             \
    _Pragma("unroll")                                                       \
    for (int k16 = 0; k16 < 2; k16++) {                                     \
        uint32_t aH[4][4];                                                  \
        _Pragma("unroll")                                                   \
        for (int mt = 0; mt < 4; mt++) {                                    \
            uint32_t o = (uint32_t)(wm * 64 + mt * 16 + a_m) * 128u + k16 * 32u + a_kc * 16u; \
            ldsm4(aH[mt], Au + sw128(o));                                   \
        }                                                                   \
        _Pragma("unroll")                                                   \
        for (int ng = 0; ng < 4; ng++) {                                    \
            uint32_t o = (k16 * 16u + t_k) * 256u                           \
                       + (uint32_t)(wn * 64 + ng * 16) * 2u + t_n8 * 16u;   \
            uint32_t bH[4];                                                 \
            ldsm4t(bH, Bhu + sw256(o));                                     \
            _Pragma("unroll")                                               \
            for (int mt = 0; mt < 4; mt++) {                                \
                mma16816h(C[mt][2 * ng],     aH[mt], bH[0], bH[1]);         \
                mma16816h(C[mt][2 * ng + 1], aH[mt], bH[2], bH[3]);         \
            }                                                               \
        }                                                                   \
    }                                                                       \
} while (0)

    LDGB2(0);
    CPA2(0, 0);
    STSB2(0);
    LDGB2(1);
    for (int c = 0; c < G2_KIT; c++) {
        int st = c & 1;
        CP_WAIT0();
        __syncthreads();
        if (c + 1 < G2_KIT) CPA2(c + 1, st ^ 1);
        COMP2(st);
        if (c + 1 < G2_KIT) STSB2(st ^ 1);
        if (c + 2 < G2_KIT) LDGB2(c + 2);
    }
    __syncthreads();

    // C -> smem fp32 [128][132]
    float* sc = (float*)sp;
#pragma unroll
    for (int mt = 0; mt < 4; mt++)
#pragma unroll
        for (int nt = 0; nt < 8; nt++) {
            int r0 = wm * 64 + mt * 16 + (lane >> 2);
            int cc = wn * 64 + nt * 8 + (lane & 3) * 2;
            sc[r0 * 132 + cc]       = C[mt][nt][0];
            sc[r0 * 132 + cc + 1]   = C[mt][nt][1];
            sc[(r0 + 8) * 132 + cc]     = C[mt][nt][2];
            sc[(r0 + 8) * 132 + cc + 1] = C[mt][nt][3];
        }
    __syncthreads();

    // weighted accumulate (K=2 commutative adds -> deterministic)
    {
        int tok = s_tok[tid];
        if (tok >= 0) {
            float wgt = s_w[tid];
            float* dst = out + (size_t)tok * Dn + d0;
#pragma unroll 8
            for (int j = 0; j < 128; j++)
                atomicAdd(dst + j, wgt * sc[tid * 132 + j]);
        }
    }
#undef LDGB2
#undef CPA2
#undef STSB2
#undef COMP2
}

// ---------------------------------------------------------------------------
extern "C" void kernel_launch(void* const* d_in, const int* in_sizes, int n_in,
                              void* d_out, int out_size) {
    const float* x   = (const float*)d_in[0];
    const float* wts = (const float*)d_in[1];
    const int*   sel = (const int*)d_in[2];
    const float* w1  = (const float*)d_in[3];
    const float* w2  = (const float*)d_in[4];
    const float* w3  = (const float*)d_in[5];
    float* out = (float*)d_out;

    cudaFuncSetAttribute(gemm1_kernel,
                         cudaFuncAttributeMaxDynamicSharedMemorySize, SMEM_REQ);
    cudaFuncSetAttribute(gemm2_kernel,
                         cudaFuncAttributeMaxDynamicSharedMemorySize, SMEM_REQ);

    route_kernel<<<1, 1024>>>(sel, wts);
    zero_kernel<<<(Tn * Dn) / 256, 256>>>(out);
    splitx_kernel<<<(Tn * Dn) / 1024, 256>>>((const float4*)x, (Tn * Dn) / 4);
    // tile index fastest: all M-tiles of one weight tile run concurrently,
    // weights stream from DRAM once and reuse via L2.
    gemm1_kernel<<<dim3(MAX_TILES, Hn / 64), 128, SMEM_REQ>>>(w1, w3);
    gemm2_kernel<<<dim3(MAX_TILES, Dn / 128), 128, SMEM_REQ>>>(w2, out);
}

// round 11
// speedup vs baseline: 3.0959x; 1.7514x over previous
#include <cuda_runtime.h>
#include <cuda_fp16.h>
#include <cstdint>

// Problem constants
#define Tn 1024
#define Dn 2048
#define Hn 7168
#define En 8
#define Kn 2
#define Pn (Tn * Kn)                   // 2048 (token,k) pairs
#define TILE_M 128
#define MAX_SLOTS (Pn + En * TILE_M)   // 3072
#define MAX_TILES (Pn / TILE_M + En)   // 24

#define G1_KIT (Dn / 32)               // 64 K-chunks of 32
#define G2_KIT (Hn / 32)               // 224 K-chunks of 32

// Dynamic smem: 2 stages x 32KB + slack (epilogue reuses as 128x132 fp32)
#define SMEM_REQ 68608

// Scratch (device globals; no allocation allowed)
__device__ int   g_slot_token[MAX_SLOTS];
__device__ float g_slot_w[MAX_SLOTS];
__device__ int   g_tile_expert[MAX_TILES];
__device__ int   g_tile_base[MAX_TILES];
// single fp16 plane for the A-side operands
__device__ __align__(16) unsigned short g_x_h[(size_t)Tn * Dn];
__device__ __align__(16) unsigned short g_hact_h[(size_t)MAX_SLOTS * Hn];

// ---------------------------------------------------------------------------
// Helpers
// ---------------------------------------------------------------------------
__device__ __forceinline__ uint32_t smem_u32(const void* p) {
    uint32_t a;
    asm("{ .reg .u64 t; cvta.to.shared.u64 t, %1; cvt.u32.u64 %0, t; }"
        : "=r"(a) : "l"(p));
    return a;
}

__device__ __forceinline__ uint32_t sw128(uint32_t o) {
    return o ^ (((o >> 7) & 7u) << 4);
}
__device__ __forceinline__ uint32_t sw256(uint32_t o) {
    return o ^ (((o >> 8) & 7u) << 4);
}

__device__ __forceinline__ void cpa16(uint32_t dst, const void* src, uint32_t sz) {
    asm volatile("cp.async.cg.shared.global [%0], [%1], 16, %2;"
                 :: "r"(dst), "l"(src), "r"(sz) : "memory");
}
#define CP_COMMIT() asm volatile("cp.async.commit_group;" ::: "memory")
#define CP_WAIT0()  asm volatile("cp.async.wait_group 0;" ::: "memory")

__device__ __forceinline__ void ldsm4(uint32_t* r, uint32_t a) {
    asm volatile("ldmatrix.sync.aligned.m8n8.x4.shared.b16 {%0,%1,%2,%3}, [%4];"
        : "=r"(r[0]), "=r"(r[1]), "=r"(r[2]), "=r"(r[3]) : "r"(a));
}
__device__ __forceinline__ void ldsm4t(uint32_t* r, uint32_t a) {
    asm volatile("ldmatrix.sync.aligned.m8n8.x4.trans.shared.b16 {%0,%1,%2,%3}, [%4];"
        : "=r"(r[0]), "=r"(r[1]), "=r"(r[2]), "=r"(r[3]) : "r"(a));
}
__device__ __forceinline__ void mma16816h(float* c, const uint32_t* a,
                                          uint32_t b0, uint32_t b1) {
    asm volatile(
        "mma.sync.aligned.m16n8k16.row.col.f32.f16.f16.f32 "
        "{%0,%1,%2,%3}, {%4,%5,%6,%7}, {%8,%9}, {%0,%1,%2,%3};"
        : "+f"(c[0]), "+f"(c[1]), "+f"(c[2]), "+f"(c[3])
        : "r"(a[0]), "r"(a[1]), "r"(a[2]), "r"(a[3]), "r"(b0), "r"(b1));
}

__device__ __forceinline__ uint32_t ph_rn(float a, float b) {
    __half2 h = __floats2half2_rn(a, b);
    return *(uint32_t*)&h;
}

// ---------------------------------------------------------------------------
// x convert: fp32 -> fp16 plane (4 MB, ~4us)
// ---------------------------------------------------------------------------
__global__ void splitx_kernel(const float4* __restrict__ src, int n4) {
    int i = blockIdx.x * blockDim.x + threadIdx.x;
    if (i < n4) {
        float4 v = __ldg(src + i);
        ((uint2*)g_x_h)[i] = make_uint2(ph_rn(v.x, v.y), ph_rn(v.z, v.w));
    }
}

// ---------------------------------------------------------------------------
// Routing
// ---------------------------------------------------------------------------
__global__ void route_kernel(const int* __restrict__ sel,
                             const float* __restrict__ wts) {
    __shared__ int s_e[Pn];
    __shared__ int s_cnt[En];
    __shared__ int s_base[En];
    int tid = threadIdx.x;

    if (tid < En) s_cnt[tid] = 0;
    __syncthreads();
    for (int i = tid; i < Pn; i += blockDim.x) {
        int e = sel[i];
        s_e[i] = e;
        atomicAdd(&s_cnt[e], 1);
    }
    __syncthreads();
    if (tid == 0) {
        int base = 0, tile = 0;
        for (int e = 0; e < En; e++) {
            s_base[e] = base;
            int padded = ((s_cnt[e] + TILE_M - 1) / TILE_M) * TILE_M;
            for (int m = 0; m < padded; m += TILE_M) {
                g_tile_expert[tile] = e;
                g_tile_base[tile]   = base + m;
                tile++;
            }
            base += padded;
        }
        for (; tile < MAX_TILES; tile++) g_tile_expert[tile] = -1;
    }
    __syncthreads();
    for (int s = tid; s < MAX_SLOTS; s += blockDim.x) g_slot_token[s] = -1;
    __syncthreads();
    for (int i = tid; i < Pn; i += blockDim.x) {
        int e = s_e[i];
        int rank = 0;
        for (int j = 0; j < i; j++) rank += (s_e[j] == e) ? 1 : 0;
        int slot = s_base[e] + rank;
        g_slot_token[slot] = i / Kn;
        g_slot_w[slot]     = wts[i];
    }
}

__global__ void zero_kernel(float* __restrict__ out) {
    int i = blockIdx.x * blockDim.x + threadIdx.x;
    out[i] = 0.0f;
}

// ---------------------------------------------------------------------------
// GEMM1: hact[slot, h0+c] = silu(x.W1^T) * (x.W3^T)
// Plain fp16. CTA 128x128 (n 0-63 gate / 64-127 up), BK=32, 4 warps 64x64.
// COALESCED loaders: A 4 threads/row (64B runs); B warp reads 4x128B lines.
// ---------------------------------------------------------------------------
__global__ __launch_bounds__(128, 2) void gemm1_kernel(
    const float* __restrict__ w1,
    const float* __restrict__ w3) {
    int e = g_tile_expert[blockIdx.x];
    if (e < 0) return;
    int base = g_tile_base[blockIdx.x];
    int h0 = blockIdx.y * 64;

    extern __shared__ char dsm[];
    __shared__ int s_tok[TILE_M];
    uint32_t raw = smem_u32(dsm);
    uint32_t sb = (raw + 1023u) & ~1023u;
    char* sp = dsm + (sb - raw);

    int tid = threadIdx.x;
    s_tok[tid] = g_slot_token[base + tid];
    __syncthreads();

    const int warp = tid >> 5, lane = tid & 31;
    const int wm = warp & 1, wn = warp >> 1;   // 2m x 2n, warp tile 64x64

    // A: thread t serves rows g*32+(t>>2), granule t&3 (16B of a 64B row run)
    const unsigned short* aP[4];
    uint32_t avz[4], adst[4];
#pragma unroll
    for (int g = 0; g < 4; g++) {
        int r = g * 32 + (tid >> 2);
        int tk = s_tok[r];
        aP[g]  = g_x_h + (size_t)(tk < 0 ? 0 : tk) * Dn + (tid & 3) * 8;
        avz[g] = (tk >= 0) ? 16u : 0u;
        adst[g] = sw128((uint32_t)r * 128u + (uint32_t)(tid & 3) * 16u);
    }

    // B: thread t serves rows g*16+(t>>3), seg t&7 (16B fp32 -> 8B fp16)
    const float* b1P = w1 + ((size_t)e * Hn + h0 + (tid >> 3)) * Dn + (tid & 7) * 4;
    const float* b3P = w3 + ((size_t)e * Hn + h0 + (tid >> 3)) * Dn + (tid & 7) * 4;
    uint32_t bdst[8];
#pragma unroll
    for (int g = 0; g < 8; g++) {
        uint32_t r = (uint32_t)(g * 16 + (tid >> 3));
        bdst[g] = sw128(r * 128u + (uint32_t)((tid & 7) >> 1) * 16u)
                + (uint32_t)((tid & 7) & 1) * 8u;
    }

    // ldmatrix lane offsets
    const uint32_t a_m  = (uint32_t)(lane & 15);
    const uint32_t a_kc = (uint32_t)(lane >> 4);
    const uint32_t b_n  = (uint32_t)((lane & 7) | ((lane >> 4) << 3));
    const uint32_t b_kc = (uint32_t)((lane >> 3) & 1);

    float C[4][8][4];
#pragma unroll
    for (int i = 0; i < 4; i++)
#pragma unroll
        for (int j = 0; j < 8; j++)
#pragma unroll
            for (int k = 0; k < 4; k++) C[i][j][k] = 0.f;

    float4 Br[8];

#define LDGB1(c) do {                                                       \
    _Pragma("unroll")                                                       \
    for (int g = 0; g < 4; g++)                                             \
        Br[g] = __ldg((const float4*)(b1P + (size_t)g * 16 * Dn + (c) * 32)); \
    _Pragma("unroll")                                                       \
    for (int g = 4; g < 8; g++)                                             \
        Br[g] = __ldg((const float4*)(b3P + (size_t)(g - 4) * 16 * Dn + (c) * 32)); \
} while (0)

#define CPA1(c, st) do {                                                    \
    uint32_t Ab = sb + (st) * 32768u;                                       \
    _Pragma("unroll")                                                       \
    for (int g = 0; g < 4; g++)                                             \
        cpa16(Ab + adst[g], aP[g] + (c) * 32, avz[g]);                      \
    CP_COMMIT();                                                            \
} while (0)

#define STSB1(st) do {                                                      \
    char* Bb = sp + (st) * 32768 + 16384;                                   \
    _Pragma("unroll")                                                       \
    for (int g = 0; g < 8; g++) {                                           \
        float4 v = Br[g];                                                   \
        *(uint2*)(Bb + bdst[g]) = make_uint2(ph_rn(v.x, v.y), ph_rn(v.z, v.w)); \
    }                                                                       \
} while (0)

#define COMP1(st) do {                                                      \
    uint32_t Au = sb + (st) * 32768u;                                       \
    uint32_t Bu = Au + 16384u;                                              \
    _Pragma("unroll")                                                       \
    for (int k16 = 0; k16 < 2; k16++) {                                     \
        uint32_t aH[4][4];                                                  \
        _Pragma("unroll")                                                   \
        for (int mt = 0; mt < 4; mt++) {                                    \
            uint32_t o = (uint32_t)(wm * 64 + mt * 16 + a_m) * 128u + k16 * 32u + a_kc * 16u; \
            ldsm4(aH[mt], Au + sw128(o));                                   \
        }                                                                   \
        _Pragma("unroll")                                                   \
        for (int ng = 0; ng < 4; ng++) {                                    \
            uint32_t o = (uint32_t)(wn * 64 + ng * 16 + b_n) * 128u + k16 * 32u + b_kc * 16u; \
            uint32_t bH[4];                                                 \
            ldsm4(bH, Bu + sw128(o));                                       \
            _Pragma("unroll")                                               \
            for (int mt = 0; mt < 4; mt++) {                                \
                mma16816h(C[mt][2 * ng],     aH[mt], bH[0], bH[1]);         \
                mma16816h(C[mt][2 * ng + 1], aH[mt], bH[2], bH[3]);         \
            }                                                               \
        }                                                                   \
    }                                                                       \
} while (0)

    LDGB1(0);
    CPA1(0, 0);
    STSB1(0);
    LDGB1(1);
    for (int c = 0; c < G1_KIT; c++) {
        int st = c & 1;
        CP_WAIT0();
        __syncthreads();
        if (c + 1 < G1_KIT) CPA1(c + 1, st ^ 1);
        COMP1(st);
        if (c + 1 < G1_KIT) STSB1(st ^ 1);
        if (c + 2 < G1_KIT) LDGB1(c + 2);
    }
    __syncthreads();

    // C -> smem fp32 [128][132]
    float* sc = (float*)sp;
#pragma unroll
    for (int mt = 0; mt < 4; mt++)
#pragma unroll
        for (int nt = 0; nt < 8; nt++) {
            int r0 = wm * 64 + mt * 16 + (lane >> 2);
            int cc = wn * 64 + nt * 8 + (lane & 3) * 2;
            sc[r0 * 132 + cc]       = C[mt][nt][0];
            sc[r0 * 132 + cc + 1]   = C[mt][nt][1];
            sc[(r0 + 8) * 132 + cc]     = C[mt][nt][2];
            sc[(r0 + 8) * 132 + cc + 1] = C[mt][nt][3];
        }
    __syncthreads();

    // SiLU(gate)*up -> g_hact fp16 plane; thread t owns row t (64 outputs)
    {
        size_t orow = (size_t)(base + tid) * Hn + h0;
#pragma unroll
        for (int j = 0; j < 64; j += 4) {
            float v[4];
#pragma unroll
            for (int jj = 0; jj < 4; jj++) {
                float g = sc[tid * 132 + j + jj];
                float u = sc[tid * 132 + 64 + j + jj];
                v[jj] = g / (1.f + __expf(-g)) * u;
            }
            *(uint2*)(g_hact_h + orow + j) =
                make_uint2(ph_rn(v[0], v[1]), ph_rn(v[2], v[3]));
        }
    }
#undef LDGB1
#undef CPA1
#undef STSB1
#undef COMP1
}

// ---------------------------------------------------------------------------
// GEMM2: out[tok, d0+c] += w * sum_h hact[slot,h] * w2[e,h,d0+c]
// Plain fp16. CTA 128x128, 4 warps 64x64, 2-stage pipeline.
// COALESCED loaders: A 4 threads/row; B warp reads one 512B row per LDG.
// ---------------------------------------------------------------------------
__global__ __launch_bounds__(128, 2) void gemm2_kernel(
    const float* __restrict__ w2,
    float* __restrict__ out) {
    int e = g_tile_expert[blockIdx.x];
    if (e < 0) return;
    int base = g_tile_base[blockIdx.x];
    int d0 = blockIdx.y * 128;

    extern __shared__ char dsm[];
    __shared__ int   s_tok[TILE_M];
    __shared__ float s_w[TILE_M];
    uint32_t raw = smem_u32(dsm);
    uint32_t sb = (raw + 1023u) & ~1023u;
    char* sp = dsm + (sb - raw);

    int tid = threadIdx.x;
    s_tok[tid] = g_slot_token[base + tid];
    s_w[tid]   = g_slot_w[base + tid];
    __syncthreads();

    const int warp = tid >> 5, lane = tid & 31;
    const int wm = warp & 1, wn = warp >> 1;

    // A: thread t serves rows g*32+(t>>2), granule t&3
    const unsigned short* aP[4];
    uint32_t adst[4];
#pragma unroll
    for (int g = 0; g < 4; g++) {
        int r = g * 32 + (tid >> 2);
        aP[g]   = g_hact_h + (size_t)(base + r) * Hn + (tid & 3) * 8;
        adst[g] = sw128((uint32_t)r * 128u + (uint32_t)(tid & 3) * 16u);
    }

    // B: warp reads k-row g*4+warp, lane covers seg=lane (16B fp32 -> 8B)
    const float* wP = w2 + ((size_t)e * Hn + warp) * Dn + d0 + lane * 4;
    uint32_t bdst[8];
#pragma unroll
    for (int g = 0; g < 8; g++) {
        uint32_t r = (uint32_t)(g * 4 + warp);
        bdst[g] = sw256(r * 256u + (uint32_t)(lane >> 1) * 16u)
                + (uint32_t)(lane & 1) * 8u;
    }

    // ldmatrix lane offsets
    const uint32_t a_m  = (uint32_t)(lane & 15);
    const uint32_t a_kc = (uint32_t)(lane >> 4);
    const uint32_t t_k  = (uint32_t)((lane & 7) | (((lane >> 3) & 1) << 3));
    const uint32_t t_n8 = (uint32_t)(lane >> 4);

    float C[4][8][4];
#pragma unroll
    for (int i = 0; i < 4; i++)
#pragma unroll
        for (int j = 0; j < 8; j++)
#pragma unroll
            for (int k = 0; k < 4; k++) C[i][j][k] = 0.f;

    float4 Br[8];

#define LDGB2(c) do {                                                       \
    _Pragma("unroll")                                                       \
    for (int g = 0; g < 8; g++)                                             \
        Br[g] = __ldg((const float4*)(wP + ((size_t)(c) * 32 + g * 4) * Dn)); \
} while (0)

#define CPA2(c, st) do {                                                    \
    uint32_t Ab = sb + (st) * 32768u;                                       \
    _Pragma("unroll")                                                       \
    for (int g = 0; g < 4; g++)                                             \
        cpa16(Ab + adst[g], aP[g] + (c) * 32, 16u);                         \
    CP_COMMIT();                                                            \
} while (0)

#define STSB2(st) do {                                                      \
    char* Bh = sp + (st) * 32768 + 16384;                                   \
    _Pragma("unroll")                                                       \
    for (int g = 0; g < 8; g++) {                                           \
        float4 v = Br[g];                                                   \
        *(uint2*)(Bh + bdst[g]) = make_uint2(ph_rn(v.x, v.y), ph_rn(v.z, v.w)); \
    }                                                                       \
} while (0)

#define COMP2(st) do {                                                      \
    uint32_t Au  = sb + (st) * 32768u;                                      \
    uint32_t Bhu = Au + 16384u;                                             \
    _Pragma("unroll")                                                       \
    for (int k16 = 0; k16 < 2; k16++) {                                     \
        uint32_t aH[4][4];                                                  \
        _Pragma("unroll")                                                   \
        for (int mt = 0; mt < 4; mt++) {                                    \
            uint32_t o = (uint32_t)(wm * 64 + mt * 16 + a_m) * 128u + k16 * 32u + a_kc * 16u; \
            ldsm4(aH[mt], Au + sw128(o));                                   \
        }                                                                   \
        _Pragma("unroll")                                                   \
        for (int ng = 0; ng < 4; ng++) {                                    \
            uint32_t o = (k16 * 16u + t_k) * 256u                           \
                       + (uint32_t)(wn * 64 + ng * 16) * 2u + t_n8 * 16u;   \
            uint32_t bH[4];                                                 \
            ldsm4t(bH, Bhu + sw256(o));                                     \
            _Pragma("unroll")                                               \
            for (int mt = 0; mt < 4; mt++) {                                \
                mma16816h(C[mt][2 * ng],     aH[mt], bH[0], bH[1]);         \
                mma16816h(C[mt][2 * ng + 1], aH[mt], bH[2], bH[3]);         \
            }                                                               \
        }                                                                   \
    }                                                                       \
} while (0)

    LDGB2(0);
    CPA2(0, 0);
    STSB2(0);
    LDGB2(1);
    for (int c = 0; c < G2_KIT; c++) {
        int st = c & 1;
        CP_WAIT0();
        __syncthreads();
        if (c + 1 < G2_KIT) CPA2(c + 1, st ^ 1);
        COMP2(st);
        if (c + 1 < G2_KIT) STSB2(st ^ 1);
        if (c + 2 < G2_KIT) LDGB2(c + 2);
    }
    __syncthreads();

    // C -> smem fp32 [128][132]
    float* sc = (float*)sp;
#pragma unroll
    for (int mt = 0; mt < 4; mt++)
#pragma unroll
        for (int nt = 0; nt < 8; nt++) {
            int r0 = wm * 64 + mt * 16 + (lane >> 2);
            int cc = wn * 64 + nt * 8 + (lane & 3) * 2;
            sc[r0 * 132 + cc]       = C[mt][nt][0];
            sc[r0 * 132 + cc + 1]   = C[mt][nt][1];
            sc[(r0 + 8) * 132 + cc]     = C[mt][nt][2];
            sc[(r0 + 8) * 132 + cc + 1] = C[mt][nt][3];
        }
    __syncthreads();

    // weighted accumulate (K=2 commutative adds -> deterministic)
    {
        int tok = s_tok[tid];
        if (tok >= 0) {
            float wgt = s_w[tid];
            float* dst = out + (size_t)tok * Dn + d0;
#pragma unroll 8
            for (int j = 0; j < 128; j++)
                atomicAdd(dst + j, wgt * sc[tid * 132 + j]);
        }
    }
#undef LDGB2
#undef CPA2
#undef STSB2
#undef COMP2
}

// ---------------------------------------------------------------------------
extern "C" void kernel_launch(void* const* d_in, const int* in_sizes, int n_in,
                              void* d_out, int out_size) {
    const float* x   = (const float*)d_in[0];
    const float* wts = (const float*)d_in[1];
    const int*   sel = (const int*)d_in[2];
    const float* w1  = (const float*)d_in[3];
    const float* w2  = (const float*)d_in[4];
    const float* w3  = (const float*)d_in[5];
    float* out = (float*)d_out;

    cudaFuncSetAttribute(gemm1_kernel,
                         cudaFuncAttributeMaxDynamicSharedMemorySize, SMEM_REQ);
    cudaFuncSetAttribute(gemm2_kernel,
                         cudaFuncAttributeMaxDynamicSharedMemorySize, SMEM_REQ);

    route_kernel<<<1, 1024>>>(sel, wts);
    zero_kernel<<<(Tn * Dn) / 256, 256>>>(out);
    splitx_kernel<<<(Tn * Dn) / 1024, 256>>>((const float4*)x, (Tn * Dn) / 4);
    // tile index fastest: all M-tiles of one weight tile run concurrently,
    // weights stream from DRAM once and reuse via L2.
    gemm1_kernel<<<dim3(MAX_TILES, Hn / 64), 128, SMEM_REQ>>>(w1, w3);
    gemm2_kernel<<<dim3(MAX_TILES, Dn / 128), 128, SMEM_REQ>>>(w2, out);
}